// round 1
// baseline (speedup 1.0000x reference)
#include <cuda_runtime.h>
#include <cuda_bf16.h>
#include <math.h>

// Problem constants
#define BATCH 2048
#define SIZE_D 2048
#define KNOTS 8
#define HID 1024
#define NC 17               // 2*K+1
#define OUTW (SIZE_D * NC)  // 34816
#define NTOT (BATCH * SIZE_D)
#define EPS_C 1e-6f

// ---------------- device scratch (allocation-free rule) ----------------
__device__ float g_h[(size_t)BATCH * HID];           // 8 MB
__device__ float g_net[(size_t)BATCH * OUTW];        // 285 MB
__device__ float g_part_s[1024];
__device__ float g_part_ss[1024];
__device__ float g_stats[2];                         // mean, invstd

// ---------------- pass 1: partial sum / sumsq ----------------
__global__ void stat_pass1(const float* __restrict__ xp, int n) {
    float s = 0.f, ss = 0.f;
    for (int i = blockIdx.x * blockDim.x + threadIdx.x; i < n;
         i += gridDim.x * blockDim.x) {
        float v = xp[i];
        s += v;
        ss += v * v;
    }
    __shared__ float shs[256];
    __shared__ float shss[256];
    int tid = threadIdx.x;
    shs[tid] = s; shss[tid] = ss;
    __syncthreads();
    for (int o = 128; o > 0; o >>= 1) {
        if (tid < o) { shs[tid] += shs[tid + o]; shss[tid] += shss[tid + o]; }
        __syncthreads();
    }
    if (tid == 0) { g_part_s[blockIdx.x] = shs[0]; g_part_ss[blockIdx.x] = shss[0]; }
}

// ---------------- pass 2: finalize mean / invstd ----------------
__global__ void stat_pass2(int nblocks, int n) {
    __shared__ float shs[1024];
    __shared__ float shss[1024];
    int tid = threadIdx.x;
    shs[tid]  = (tid < nblocks) ? g_part_s[tid]  : 0.f;
    shss[tid] = (tid < nblocks) ? g_part_ss[tid] : 0.f;
    __syncthreads();
    for (int o = 512; o > 0; o >>= 1) {
        if (tid < o) { shs[tid] += shs[tid + o]; shss[tid] += shss[tid + o]; }
        __syncthreads();
    }
    if (tid == 0) {
        float S = shs[0], SS = shss[0];
        float mean = S / (float)n;
        float var = (SS - S * mean) / (float)(n - 1);   // ddof=1
        g_stats[0] = mean;
        g_stats[1] = rsqrtf(var);
    }
}

// ---------------- tiled fp32 GEMM + tanh epilogue ----------------
// C[M,N] = tanh(A'[M,K] @ B[K,N] + bias),  A' = (A - mean)*invstd if NORM
// BM=BN=128, BK=8, 256 threads, 8x8 per-thread tile. All dims divide evenly.
template <bool NORM>
__global__ __launch_bounds__(256)
void gemm_tanh(const float* __restrict__ A, const float* __restrict__ Bm,
               const float* __restrict__ bias, float* __restrict__ C,
               int M, int N, int Kd) {
    __shared__ float As[8][128];   // [k][m] transposed
    __shared__ float Bs[8][128];   // [k][n]

    const int tid = threadIdx.x;
    const int tx = tid & 15;       // 0..15 -> N direction
    const int ty = tid >> 4;       // 0..15 -> M direction
    const int bx = blockIdx.x;     // N tile
    const int by = blockIdx.y;     // M tile

    float mean = 0.f, invstd = 1.f;
    if (NORM) { mean = g_stats[0]; invstd = g_stats[1]; }

    // A tile load mapping: 128 rows x 8 cols, one float4 per thread
    const int a_row = tid >> 1;            // 0..127
    const int a_col = (tid & 1) * 4;       // 0 or 4
    // B tile load mapping: 8 rows x 128 cols, one float4 per thread
    const int b_row = tid >> 5;            // 0..7
    const int b_col = (tid & 31) * 4;      // 0..124

    const float* Aptr = A + (size_t)(by * 128 + a_row) * Kd + a_col;
    const float* Bptr = Bm + (size_t)b_row * N + bx * 128 + b_col;

    float acc[8][8];
#pragma unroll
    for (int i = 0; i < 8; i++)
#pragma unroll
        for (int j = 0; j < 8; j++) acc[i][j] = 0.f;

    for (int k0 = 0; k0 < Kd; k0 += 8) {
        float4 av = *(const float4*)(Aptr + k0);
        if (NORM) {
            av.x = (av.x - mean) * invstd;
            av.y = (av.y - mean) * invstd;
            av.z = (av.z - mean) * invstd;
            av.w = (av.w - mean) * invstd;
        }
        As[a_col + 0][a_row] = av.x;
        As[a_col + 1][a_row] = av.y;
        As[a_col + 2][a_row] = av.z;
        As[a_col + 3][a_row] = av.w;

        float4 bv = *(const float4*)(Bptr + (size_t)k0 * N);
        *(float4*)&Bs[b_row][b_col] = bv;

        __syncthreads();

#pragma unroll
        for (int kk = 0; kk < 8; kk++) {
            float4 a0 = *(const float4*)&As[kk][ty * 8];
            float4 a1 = *(const float4*)&As[kk][ty * 8 + 4];
            float4 b0 = *(const float4*)&Bs[kk][tx * 8];
            float4 b1 = *(const float4*)&Bs[kk][tx * 8 + 4];
            float ra[8] = {a0.x, a0.y, a0.z, a0.w, a1.x, a1.y, a1.z, a1.w};
            float rb[8] = {b0.x, b0.y, b0.z, b0.w, b1.x, b1.y, b1.z, b1.w};
#pragma unroll
            for (int i = 0; i < 8; i++)
#pragma unroll
                for (int j = 0; j < 8; j++)
                    acc[i][j] = fmaf(ra[i], rb[j], acc[i][j]);
        }
        __syncthreads();
    }

    // epilogue: bias + tanh
    const int col0 = bx * 128 + tx * 8;
    float bj[8];
#pragma unroll
    for (int j = 0; j < 8; j++) bj[j] = bias[col0 + j];

#pragma unroll
    for (int i = 0; i < 8; i++) {
        size_t row = (size_t)(by * 128 + ty * 8 + i);
        float4 o0, o1;
        o0.x = tanhf(acc[i][0] + bj[0]);
        o0.y = tanhf(acc[i][1] + bj[1]);
        o0.z = tanhf(acc[i][2] + bj[2]);
        o0.w = tanhf(acc[i][3] + bj[3]);
        o1.x = tanhf(acc[i][4] + bj[4]);
        o1.y = tanhf(acc[i][5] + bj[5]);
        o1.z = tanhf(acc[i][6] + bj[6]);
        o1.w = tanhf(acc[i][7] + bj[7]);
        *(float4*)(C + row * N + col0)     = o0;
        *(float4*)(C + row * N + col0 + 4) = o1;
    }
}

// ---------------- spline evaluation + per-row log reduction ----------------
// One block per batch row b. 8 chunks of 256 s-values, staged through smem.
__global__ __launch_bounds__(256)
void spline_kernel(const float* __restrict__ net, const float* __restrict__ x_in,
                   const float* __restrict__ logd, float* __restrict__ phi_out,
                   float* __restrict__ log_out) {
    const int b = blockIdx.x;
    const int tid = threadIdx.x;
    const float* row = net + (size_t)b * OUTW;

    __shared__ float sh[256 * NC];   // 17408 B
    __shared__ float red[256];

    float lsum = 0.f;

    for (int chunk = 0; chunk < 8; chunk++) {
        __syncthreads();
        for (int i = tid; i < 256 * NC; i += 256)
            sh[i] = row[chunk * 256 * NC + i];
        __syncthreads();

        const int s = chunk * 256 + tid;
        const float* p = sh + tid * NC;

        float hr[9], wr[8];
#pragma unroll
        for (int c = 0; c < 9; c++) hr[c] = p[c];
#pragma unroll
        for (int c = 0; c < 8; c++) wr[c] = p[9 + c];

        // softmax over wr
        float m = wr[0];
#pragma unroll
        for (int c = 1; c < 8; c++) m = fmaxf(m, wr[c]);
        float wn[8];
        float wsum = 0.f;
#pragma unroll
        for (int c = 0; c < 8; c++) { wn[c] = expf(wr[c] - m); wsum += wn[c]; }
        float winv = 1.0f / wsum;
#pragma unroll
        for (int c = 0; c < 8; c++) wn[c] *= winv;

        // normalized heights
        float eh[9];
#pragma unroll
        for (int c = 0; c < 9; c++) eh[c] = expf(hr[c]);
        float denom = 0.f;
#pragma unroll
        for (int c = 0; c < 8; c++) denom += 0.5f * wn[c] * (eh[c] + eh[c + 1]);
        float dinv = 1.0f / denom;
        float hn[9];
#pragma unroll
        for (int c = 0; c < 9; c++) hn[c] = eh[c] * dinv;

        const float x = x_in[(size_t)b * SIZE_D + s] * 0.31830988618379067154f; // 1/pi

        // bin selection (monotone prefix): k = #{cumsum < x}, clipped to 7
        float cum = 0.f, phicum = 0.f;
        float wk = wn[0], hk = hn[0], hk1 = hn[1];
        float xkm1 = -EPS_C, phikm1 = 0.f;
#pragma unroll
        for (int i = 0; i < 7; i++) {
            float trap = 0.5f * wn[i] * (hn[i] + hn[i + 1]);
            cum += wn[i];
            phicum += trap;
            bool c = (cum < x);
            wk     = c ? wn[i + 1] : wk;
            hk     = c ? hn[i + 1] : hk;
            hk1    = c ? hn[i + 2] : hk1;
            xkm1   = c ? cum      : xkm1;
            phikm1 = c ? phicum   : phikm1;
        }

        float alpha = (x - xkm1) / wk;
        float phi = phikm1 + alpha * hk * wk
                  + 0.5f * alpha * alpha * (hk1 - hk) * wk;
        phi_out[(size_t)b * SIZE_D + s] = phi;
        lsum += logf(hk + alpha * (hk1 - hk));
    }

    red[tid] = lsum;
    __syncthreads();
    for (int o = 128; o > 0; o >>= 1) {
        if (tid < o) red[tid] += red[tid + o];
        __syncthreads();
    }
    if (tid == 0) log_out[b] = logd[b] - red[0];
}

// ---------------- launch ----------------
extern "C" void kernel_launch(void* const* d_in, const int* in_sizes, int n_in,
                              void* d_out, int out_size) {
    (void)in_sizes; (void)n_in; (void)out_size;
    const float* x_in      = (const float*)d_in[0];
    const float* x_passive = (const float*)d_in[1];
    const float* log_dens  = (const float*)d_in[2];
    const float* w1        = (const float*)d_in[3];
    const float* b1        = (const float*)d_in[4];
    const float* w2        = (const float*)d_in[5];
    const float* b2        = (const float*)d_in[6];

    float* out_phi = (float*)d_out;                        // [2048, 2048]
    float* out_log = (float*)d_out + (size_t)NTOT;         // [2048]

    float* hbuf; cudaGetSymbolAddress((void**)&hbuf, g_h);
    float* nbuf; cudaGetSymbolAddress((void**)&nbuf, g_net);

    // 1) global mean / std of x_passive
    stat_pass1<<<1024, 256>>>(x_passive, NTOT);
    stat_pass2<<<1, 1024>>>(1024, NTOT);

    // 2) h = tanh(xs @ w1 + b1)   [2048 x 1024]
    gemm_tanh<true><<<dim3(HID / 128, BATCH / 128), 256>>>(
        x_passive, w1, b1, hbuf, BATCH, HID, SIZE_D);

    // 3) net = tanh(h @ w2 + b2)  [2048 x 34816]
    gemm_tanh<false><<<dim3(OUTW / 128, BATCH / 128), 256>>>(
        hbuf, w2, b2, nbuf, BATCH, OUTW, HID);

    // 4) spline + per-row log-density reduction
    spline_kernel<<<BATCH, 256>>>(nbuf, x_in, log_dens, out_phi, out_log);
}

// round 3
// speedup vs baseline: 2.2065x; 2.2065x over previous
#include <cuda_runtime.h>
#include <cuda_bf16.h>
#include <math.h>
#include <stdint.h>

// ---------------- problem constants ----------------
#define BATCH 2048
#define SIZE_D 2048
#define HID 1024
#define NC 17
#define OUTW (SIZE_D * NC)   // 34816
#define NTOT (BATCH * SIZE_D)
#define EPS_C 1e-6f

// ---------------- GEMM tiling ----------------
#define GBM 128
#define GBN 128
#define GBK 32
#define GSTAGES 4
#define TILE_B (GBM * 64)        // one tile: 128 rows x 32 bf16 = 64B/row = 8192B
#define STAGE_B (4 * TILE_B)     // Ahi,Alo,Bhi,Blo = 32768B
#define GEMM_SMEM (GSTAGES * STAGE_B)  // 131072

// ---------------- device scratch (allocation-free rule) ----------------
__device__ __nv_bfloat16 g_xhi[(size_t)NTOT];
__device__ __nv_bfloat16 g_xlo[(size_t)NTOT];
__device__ __nv_bfloat16 g_w1t_hi[(size_t)HID * SIZE_D];   // [1024][2048]
__device__ __nv_bfloat16 g_w1t_lo[(size_t)HID * SIZE_D];
__device__ __nv_bfloat16 g_hhi[(size_t)BATCH * HID];
__device__ __nv_bfloat16 g_hlo[(size_t)BATCH * HID];
__device__ __nv_bfloat16 g_w2t_hi[(size_t)OUTW * HID];     // [34816][1024]
__device__ __nv_bfloat16 g_w2t_lo[(size_t)OUTW * HID];
__device__ float g_net[(size_t)BATCH * OUTW];              // 285 MB
__device__ float g_colsum[HID];
__device__ float g_part_s[1024];
__device__ float g_part_ss[1024];
__device__ float g_stats[2];                               // mean, invstd

// ---------------- small PTX helpers (all <= sm_80 features) ----------------
__device__ __forceinline__ uint32_t smem_u32(const void* p) {
    uint32_t a;
    asm("{ .reg .u64 t; cvta.to.shared.u64 t, %1; cvt.u32.u64 %0, t; }"
        : "=r"(a) : "l"(p));
    return a;
}

__device__ __forceinline__ void cp_async16(uint32_t sa, const void* ga) {
    asm volatile("cp.async.cg.shared.global [%0], [%1], 16;"
                 :: "r"(sa), "l"(ga) : "memory");
}
__device__ __forceinline__ void cp_commit() {
    asm volatile("cp.async.commit_group;" ::: "memory");
}
template <int N>
__device__ __forceinline__ void cp_wait() {
    asm volatile("cp.async.wait_group %0;" :: "n"(N) : "memory");
}

__device__ __forceinline__ void ldmatrix_x4(uint32_t* r, uint32_t addr) {
    asm volatile("ldmatrix.sync.aligned.m8n8.x4.shared.b16 {%0,%1,%2,%3}, [%4];"
                 : "=r"(r[0]), "=r"(r[1]), "=r"(r[2]), "=r"(r[3])
                 : "r"(addr));
}

__device__ __forceinline__ void mma16816(float* c, const uint32_t* a,
                                         uint32_t b0, uint32_t b1) {
    asm volatile(
        "mma.sync.aligned.m16n8k16.row.col.f32.bf16.bf16.f32 "
        "{%0,%1,%2,%3}, {%4,%5,%6,%7}, {%8,%9}, {%0,%1,%2,%3};"
        : "+f"(c[0]), "+f"(c[1]), "+f"(c[2]), "+f"(c[3])
        : "r"(a[0]), "r"(a[1]), "r"(a[2]), "r"(a[3]), "r"(b0), "r"(b1));
}

// swizzled byte offset of (row, 16B-chunk) inside a 128x64B tile
__device__ __forceinline__ uint32_t sw_off(int row, int ch) {
    return ((uint32_t)row << 6) + (((ch ^ (row >> 1)) & 3) << 4);
}

// ---------------- stats ----------------
__global__ void stat_pass1(const float* __restrict__ xp, int n) {
    float s = 0.f, ss = 0.f;
    for (int i = blockIdx.x * blockDim.x + threadIdx.x; i < n;
         i += gridDim.x * blockDim.x) {
        float v = xp[i];
        s += v; ss += v * v;
    }
    __shared__ float shs[256];
    __shared__ float shss[256];
    int tid = threadIdx.x;
    shs[tid] = s; shss[tid] = ss;
    __syncthreads();
    for (int o = 128; o > 0; o >>= 1) {
        if (tid < o) { shs[tid] += shs[tid + o]; shss[tid] += shss[tid + o]; }
        __syncthreads();
    }
    if (tid == 0) { g_part_s[blockIdx.x] = shs[0]; g_part_ss[blockIdx.x] = shss[0]; }
}

__global__ void stat_pass2(int nblocks, int n) {
    __shared__ float shs[1024];
    __shared__ float shss[1024];
    int tid = threadIdx.x;
    shs[tid]  = (tid < nblocks) ? g_part_s[tid]  : 0.f;
    shss[tid] = (tid < nblocks) ? g_part_ss[tid] : 0.f;
    __syncthreads();
    for (int o = 512; o > 0; o >>= 1) {
        if (tid < o) { shs[tid] += shs[tid + o]; shss[tid] += shss[tid + o]; }
        __syncthreads();
    }
    if (tid == 0) {
        float S = shs[0], SS = shss[0];
        float mean = S / (float)n;
        float var = (SS - S * mean) / (float)(n - 1);
        g_stats[0] = mean;
        g_stats[1] = rsqrtf(var);
    }
}

// ---------------- prep kernels ----------------
__global__ void split_x(const float* __restrict__ x,
                        __nv_bfloat16* __restrict__ hi,
                        __nv_bfloat16* __restrict__ lo) {
    int i = blockIdx.x * blockDim.x + threadIdx.x;   // one float4 per thread
    float4 v = ((const float4*)x)[i];
    __nv_bfloat16 h0 = __float2bfloat16(v.x);
    __nv_bfloat16 h1 = __float2bfloat16(v.y);
    __nv_bfloat16 h2 = __float2bfloat16(v.z);
    __nv_bfloat16 h3 = __float2bfloat16(v.w);
    __nv_bfloat16 l0 = __float2bfloat16(v.x - __bfloat162float(h0));
    __nv_bfloat16 l1 = __float2bfloat16(v.y - __bfloat162float(h1));
    __nv_bfloat16 l2 = __float2bfloat16(v.z - __bfloat162float(h2));
    __nv_bfloat16 l3 = __float2bfloat16(v.w - __bfloat162float(h3));
    __nv_bfloat162 hp0 = {h0, h1}, hp1 = {h2, h3};
    __nv_bfloat162 lp0 = {l0, l1}, lp1 = {l2, l3};
    uint2 hv = {*(uint32_t*)&hp0, *(uint32_t*)&hp1};
    uint2 lv = {*(uint32_t*)&lp0, *(uint32_t*)&lp1};
    ((uint2*)hi)[i] = hv;
    ((uint2*)lo)[i] = lv;
}

// src [K][N] fp32 -> dst hi/lo [N][K] bf16
__global__ __launch_bounds__(256)
void transpose_split(const float* __restrict__ src,
                     __nv_bfloat16* __restrict__ dhi,
                     __nv_bfloat16* __restrict__ dlo, int K, int N) {
    __shared__ float t[32][33];
    const int n0 = blockIdx.x * 32;
    const int k0 = blockIdx.y * 32;
    const int tx = threadIdx.x & 31;
    const int ty = threadIdx.x >> 5;
#pragma unroll
    for (int i = 0; i < 32; i += 8)
        t[ty + i][tx] = src[(size_t)(k0 + ty + i) * N + n0 + tx];
    __syncthreads();
#pragma unroll
    for (int i = 0; i < 32; i += 8) {
        float v = t[tx][ty + i];
        __nv_bfloat16 h = __float2bfloat16(v);
        __nv_bfloat16 l = __float2bfloat16(v - __bfloat162float(h));
        size_t o = (size_t)(n0 + ty + i) * K + k0 + tx;
        dhi[o] = h;
        dlo[o] = l;
    }
}

__global__ void colsum_kernel(const float* __restrict__ w, float* __restrict__ out,
                              int K, int N) {
    int j = blockIdx.x * blockDim.x + threadIdx.x;
    if (j >= N) return;
    float s = 0.f;
    for (int k = 0; k < K; k++) s += w[(size_t)k * N + j];
    out[j] = s;
}

// ---------------- bf16 3-split GEMM ----------------
// C[M,N] = tanh(scale * (A @ B^T) + bias_eff)
//   EPI==0 (GEMM1): scale=invstd, bias_eff=b1-mean*invstd*colsum -> split bf16 out
//   EPI==1 (GEMM2): scale=1, bias_eff=bias                        -> fp32 out
// A hi/lo: [M][K] bf16 row-major; B hi/lo: [N][K] bf16 row-major.
template <int EPI>
__global__ __launch_bounds__(256)
void gemm_bf16(const __nv_bfloat16* __restrict__ Ahi,
               const __nv_bfloat16* __restrict__ Alo,
               const __nv_bfloat16* __restrict__ Bhi,
               const __nv_bfloat16* __restrict__ Blo,
               const float* __restrict__ bias,
               const float* __restrict__ colsum,
               float* __restrict__ Cf,
               __nv_bfloat16* __restrict__ Chi,
               __nv_bfloat16* __restrict__ Clo,
               int K, int Nout, int KTILES) {
    extern __shared__ __align__(128) char smem[];
    const uint32_t sb = smem_u32(smem);
    const int tid = threadIdx.x;
    const int wid = tid >> 5;
    const int lane = tid & 31;
    const int wm = wid & 3;       // M warp 0..3
    const int wn = wid >> 2;      // N warp 0..1
    const int m0 = blockIdx.x * GBM;
    const int n0 = blockIdx.y * GBN;

    // cp.async assignment: thread covers chunk ids tid and tid+256 of each tile
    const int r0c = tid >> 2, c0c = tid & 3;           // cid = tid
    const int r1c = (tid + 256) >> 2, c1c = tid & 3;   // cid = tid+256

    float acc[2][8][4];
#pragma unroll
    for (int a = 0; a < 2; a++)
#pragma unroll
        for (int b = 0; b < 8; b++)
#pragma unroll
            for (int c = 0; c < 4; c++) acc[a][b][c] = 0.f;

    auto load_stage = [&](int s, int kt) {
        const uint32_t base = sb + s * STAGE_B;
        const size_t kof = (size_t)kt * GBK;
        // chunk 0
        {
            uint32_t so = sw_off(r0c, c0c);
            size_t ga = (size_t)(m0 + r0c) * K + kof + c0c * 8;
            size_t gb = (size_t)(n0 + r0c) * K + kof + c0c * 8;
            cp_async16(base + 0 * TILE_B + so, Ahi + ga);
            cp_async16(base + 1 * TILE_B + so, Alo + ga);
            cp_async16(base + 2 * TILE_B + so, Bhi + gb);
            cp_async16(base + 3 * TILE_B + so, Blo + gb);
        }
        // chunk 1
        {
            uint32_t so = sw_off(r1c, c1c);
            size_t ga = (size_t)(m0 + r1c) * K + kof + c1c * 8;
            size_t gb = (size_t)(n0 + r1c) * K + kof + c1c * 8;
            cp_async16(base + 0 * TILE_B + so, Ahi + ga);
            cp_async16(base + 1 * TILE_B + so, Alo + ga);
            cp_async16(base + 2 * TILE_B + so, Bhi + gb);
            cp_async16(base + 3 * TILE_B + so, Blo + gb);
        }
    };

    // prologue: fill STAGES-1 stages
#pragma unroll
    for (int s = 0; s < GSTAGES - 1; s++) {
        load_stage(s, s);
        cp_commit();
    }

    const int lrow = lane & 15;
    const int lhalf = lane >> 4;

    for (int kt = 0; kt < KTILES; kt++) {
        cp_wait<GSTAGES - 2>();
        __syncthreads();

        const int s = kt & (GSTAGES - 1);
        const uint32_t sAhi = sb + s * STAGE_B;
        const uint32_t sAlo = sAhi + TILE_B;
        const uint32_t sBhi = sAhi + 2 * TILE_B;
        const uint32_t sBlo = sAhi + 3 * TILE_B;

#pragma unroll
        for (int k16 = 0; k16 < 2; k16++) {
            const int kc = k16 * 2 + lhalf;
            uint32_t ahi[2][4], alo[2][4];
#pragma unroll
            for (int mt = 0; mt < 2; mt++) {
                int row = wm * 32 + mt * 16 + lrow;
                uint32_t off = sw_off(row, kc);
                ldmatrix_x4(ahi[mt], sAhi + off);
                ldmatrix_x4(alo[mt], sAlo + off);
            }
            uint32_t bhi[4][4], blo[4][4];
#pragma unroll
            for (int ng = 0; ng < 4; ng++) {
                int row = wn * 64 + ng * 16 + lrow;
                uint32_t off = sw_off(row, kc);
                ldmatrix_x4(bhi[ng], sBhi + off);
                ldmatrix_x4(blo[ng], sBlo + off);
            }
#pragma unroll
            for (int mt = 0; mt < 2; mt++) {
#pragma unroll
                for (int nf = 0; nf < 8; nf++) {
                    const int g = nf >> 1, p = nf & 1;
                    uint32_t b0h = bhi[g][p],     b1h = bhi[g][2 + p];
                    uint32_t b0l = blo[g][p],     b1l = blo[g][2 + p];
                    mma16816(acc[mt][nf], ahi[mt], b0h, b1h);
                    mma16816(acc[mt][nf], ahi[mt], b0l, b1l);
                    mma16816(acc[mt][nf], alo[mt], b0h, b1h);
                }
            }
        }
        __syncthreads();
        const int nk = kt + GSTAGES - 1;
        if (nk < KTILES) load_stage(nk & (GSTAGES - 1), nk);
        cp_commit();
    }

    // ---------------- epilogue ----------------
    float mean = 0.f, invstd = 1.f;
    if (EPI == 0) { mean = g_stats[0]; invstd = g_stats[1]; }

    const int r_base = m0 + wm * 32 + (lane >> 2);
    const int c_base = n0 + wn * 64 + (lane & 3) * 2;

#pragma unroll
    for (int mt = 0; mt < 2; mt++) {
#pragma unroll
        for (int nf = 0; nf < 8; nf++) {
            const int col = c_base + nf * 8;
            float be0, be1;
            if (EPI == 0) {
                be0 = bias[col]     - mean * invstd * colsum[col];
                be1 = bias[col + 1] - mean * invstd * colsum[col + 1];
            } else {
                be0 = bias[col];
                be1 = bias[col + 1];
            }
#pragma unroll
            for (int hh = 0; hh < 2; hh++) {
                const int row = r_base + mt * 16 + hh * 8;
                float v0 = acc[mt][nf][hh * 2 + 0];
                float v1 = acc[mt][nf][hh * 2 + 1];
                if (EPI == 0) {
                    v0 = tanhf(fmaf(invstd, v0, be0));
                    v1 = tanhf(fmaf(invstd, v1, be1));
                    __nv_bfloat16 h0 = __float2bfloat16(v0);
                    __nv_bfloat16 h1 = __float2bfloat16(v1);
                    __nv_bfloat16 l0 = __float2bfloat16(v0 - __bfloat162float(h0));
                    __nv_bfloat16 l1 = __float2bfloat16(v1 - __bfloat162float(h1));
                    __nv_bfloat162 hp = {h0, h1};
                    __nv_bfloat162 lp = {l0, l1};
                    *(__nv_bfloat162*)(Chi + (size_t)row * Nout + col) = hp;
                    *(__nv_bfloat162*)(Clo + (size_t)row * Nout + col) = lp;
                } else {
                    float2 o;
                    o.x = tanhf(v0 + be0);
                    o.y = tanhf(v1 + be1);
                    *(float2*)(Cf + (size_t)row * Nout + col) = o;
                }
            }
        }
    }
}

// ---------------- spline evaluation + per-row log reduction ----------------
__global__ __launch_bounds__(256)
void spline_kernel(const float* __restrict__ net, const float* __restrict__ x_in,
                   const float* __restrict__ logd, float* __restrict__ phi_out,
                   float* __restrict__ log_out) {
    const int b = blockIdx.x;
    const int tid = threadIdx.x;
    const float* row = net + (size_t)b * OUTW;

    __shared__ float sh[256 * NC];
    __shared__ float red[256];

    float lsum = 0.f;

    for (int chunk = 0; chunk < 8; chunk++) {
        __syncthreads();
        for (int i = tid; i < 256 * NC; i += 256)
            sh[i] = row[chunk * 256 * NC + i];
        __syncthreads();

        const int s = chunk * 256 + tid;
        const float* p = sh + tid * NC;

        float hr[9], wr[8];
#pragma unroll
        for (int c = 0; c < 9; c++) hr[c] = p[c];
#pragma unroll
        for (int c = 0; c < 8; c++) wr[c] = p[9 + c];

        float m = wr[0];
#pragma unroll
        for (int c = 1; c < 8; c++) m = fmaxf(m, wr[c]);
        float wn[8];
        float wsum = 0.f;
#pragma unroll
        for (int c = 0; c < 8; c++) { wn[c] = expf(wr[c] - m); wsum += wn[c]; }
        float winv = 1.0f / wsum;
#pragma unroll
        for (int c = 0; c < 8; c++) wn[c] *= winv;

        float eh[9];
#pragma unroll
        for (int c = 0; c < 9; c++) eh[c] = expf(hr[c]);
        float denom = 0.f;
#pragma unroll
        for (int c = 0; c < 8; c++) denom += 0.5f * wn[c] * (eh[c] + eh[c + 1]);
        float dinv = 1.0f / denom;
        float hn[9];
#pragma unroll
        for (int c = 0; c < 9; c++) hn[c] = eh[c] * dinv;

        const float x = x_in[(size_t)b * SIZE_D + s] * 0.31830988618379067154f;

        float cum = 0.f, phicum = 0.f;
        float wk = wn[0], hk = hn[0], hk1 = hn[1];
        float xkm1 = -EPS_C, phikm1 = 0.f;
#pragma unroll
        for (int i = 0; i < 7; i++) {
            float trap = 0.5f * wn[i] * (hn[i] + hn[i + 1]);
            cum += wn[i];
            phicum += trap;
            bool c = (cum < x);
            wk     = c ? wn[i + 1] : wk;
            hk     = c ? hn[i + 1] : hk;
            hk1    = c ? hn[i + 2] : hk1;
            xkm1   = c ? cum      : xkm1;
            phikm1 = c ? phicum   : phikm1;
        }

        float alpha = (x - xkm1) / wk;
        float phi = phikm1 + alpha * hk * wk
                  + 0.5f * alpha * alpha * (hk1 - hk) * wk;
        phi_out[(size_t)b * SIZE_D + s] = phi;
        lsum += logf(hk + alpha * (hk1 - hk));
    }

    red[tid] = lsum;
    __syncthreads();
    for (int o = 128; o > 0; o >>= 1) {
        if (tid < o) red[tid] += red[tid + o];
        __syncthreads();
    }
    if (tid == 0) log_out[b] = logd[b] - red[0];
}

// ---------------- launch ----------------
extern "C" void kernel_launch(void* const* d_in, const int* in_sizes, int n_in,
                              void* d_out, int out_size) {
    (void)in_sizes; (void)n_in; (void)out_size;
    const float* x_in      = (const float*)d_in[0];
    const float* x_passive = (const float*)d_in[1];
    const float* log_dens  = (const float*)d_in[2];
    const float* w1        = (const float*)d_in[3];
    const float* b1        = (const float*)d_in[4];
    const float* w2        = (const float*)d_in[5];
    const float* b2        = (const float*)d_in[6];

    float* out_phi = (float*)d_out;
    float* out_log = (float*)d_out + (size_t)NTOT;

    __nv_bfloat16 *xhi, *xlo, *w1thi, *w1tlo, *hhi, *hlo, *w2thi, *w2tlo;
    float *nbuf, *csum;
    cudaGetSymbolAddress((void**)&xhi, g_xhi);
    cudaGetSymbolAddress((void**)&xlo, g_xlo);
    cudaGetSymbolAddress((void**)&w1thi, g_w1t_hi);
    cudaGetSymbolAddress((void**)&w1tlo, g_w1t_lo);
    cudaGetSymbolAddress((void**)&hhi, g_hhi);
    cudaGetSymbolAddress((void**)&hlo, g_hlo);
    cudaGetSymbolAddress((void**)&w2thi, g_w2t_hi);
    cudaGetSymbolAddress((void**)&w2tlo, g_w2t_lo);
    cudaGetSymbolAddress((void**)&nbuf, g_net);
    cudaGetSymbolAddress((void**)&csum, g_colsum);

    cudaFuncSetAttribute(gemm_bf16<0>, cudaFuncAttributeMaxDynamicSharedMemorySize,
                         GEMM_SMEM);
    cudaFuncSetAttribute(gemm_bf16<1>, cudaFuncAttributeMaxDynamicSharedMemorySize,
                         GEMM_SMEM);

    // stats on x_passive
    stat_pass1<<<1024, 256>>>(x_passive, NTOT);
    stat_pass2<<<1, 1024>>>(1024, NTOT);

    // preps
    split_x<<<NTOT / 4 / 256, 256>>>(x_passive, xhi, xlo);
    colsum_kernel<<<HID / 256, 256>>>(w1, csum, SIZE_D, HID);
    transpose_split<<<dim3(HID / 32, SIZE_D / 32), 256>>>(w1, w1thi, w1tlo,
                                                          SIZE_D, HID);
    transpose_split<<<dim3(OUTW / 32, HID / 32), 256>>>(w2, w2thi, w2tlo,
                                                        HID, OUTW);

    // GEMM1: h = tanh(xs @ w1 + b1) -> bf16 hi/lo   [2048 x 1024], K=2048
    gemm_bf16<0><<<dim3(BATCH / GBM, HID / GBN), 256, GEMM_SMEM>>>(
        xhi, xlo, w1thi, w1tlo, b1, csum,
        nullptr, hhi, hlo, SIZE_D, HID, SIZE_D / GBK);

    // GEMM2: net = tanh(h @ w2 + b2) -> fp32        [2048 x 34816], K=1024
    gemm_bf16<1><<<dim3(BATCH / GBM, OUTW / GBN), 256, GEMM_SMEM>>>(
        hhi, hlo, w2thi, w2tlo, b2, nullptr,
        nbuf, nullptr, nullptr, HID, OUTW, HID / GBK);

    // spline + per-row log-density reduction
    spline_kernel<<<BATCH, 256>>>(nbuf, x_in, log_dens, out_phi, out_log);
}

// round 5
// speedup vs baseline: 2.8896x; 1.3096x over previous
#include <cuda_runtime.h>
#include <cuda_bf16.h>
#include <math.h>
#include <stdint.h>

// ---------------- problem constants ----------------
#define BATCH 2048
#define SIZE_D 2048
#define HID 1024
#define NC 17
#define OUTW (SIZE_D * NC)   // 34816
#define NTOT (BATCH * SIZE_D)
#define EPS_C 1e-6f
#define NSTATBLK (NTOT / 4 / 256)   // 4096

// ---------------- GEMM tiling ----------------
#define GBM 128
#define GBN 128
#define GBK 32
#define GSTAGES 3
#define TILE_B (GBM * 64)        // 128 rows x 32 bf16 (64B/row) = 8192B
#define STAGE_B (4 * TILE_B)     // Ahi,Alo,Bhi,Blo = 32768B
#define GEMM_SMEM (GSTAGES * STAGE_B)  // 98304 -> 2 CTAs/SM possible

// ---------------- device scratch (allocation-free rule) ----------------
__device__ __nv_bfloat16 g_xhi[(size_t)NTOT];
__device__ __nv_bfloat16 g_xlo[(size_t)NTOT];
__device__ __nv_bfloat16 g_w1t_hi[(size_t)HID * SIZE_D];
__device__ __nv_bfloat16 g_w1t_lo[(size_t)HID * SIZE_D];
__device__ __nv_bfloat16 g_hhi[(size_t)BATCH * HID];
__device__ __nv_bfloat16 g_hlo[(size_t)BATCH * HID];
__device__ __nv_bfloat16 g_w2t_hi[(size_t)OUTW * HID];
__device__ __nv_bfloat16 g_w2t_lo[(size_t)OUTW * HID];
__device__ float g_net[(size_t)BATCH * OUTW];
__device__ float g_colsum[HID];
__device__ float g_part_s[NSTATBLK];    // FIX: was 2048, stat_split has 4096 blocks
__device__ float g_part_ss[NSTATBLK];   // FIX: was 2048
__device__ float g_stats[2];

// ---------------- PTX helpers ----------------
__device__ __forceinline__ uint32_t smem_u32(const void* p) {
    uint32_t a;
    asm("{ .reg .u64 t; cvta.to.shared.u64 t, %1; cvt.u32.u64 %0, t; }"
        : "=r"(a) : "l"(p));
    return a;
}
__device__ __forceinline__ void cp_async16(uint32_t sa, const void* ga) {
    asm volatile("cp.async.cg.shared.global [%0], [%1], 16;"
                 :: "r"(sa), "l"(ga) : "memory");
}
__device__ __forceinline__ void cp_commit() {
    asm volatile("cp.async.commit_group;" ::: "memory");
}
template <int N>
__device__ __forceinline__ void cp_wait() {
    asm volatile("cp.async.wait_group %0;" :: "n"(N) : "memory");
}
__device__ __forceinline__ void ldmatrix_x4(uint32_t* r, uint32_t addr) {
    asm volatile("ldmatrix.sync.aligned.m8n8.x4.shared.b16 {%0,%1,%2,%3}, [%4];"
                 : "=r"(r[0]), "=r"(r[1]), "=r"(r[2]), "=r"(r[3])
                 : "r"(addr));
}
__device__ __forceinline__ void mma16816(float* c, const uint32_t* a,
                                         uint32_t b0, uint32_t b1) {
    asm volatile(
        "mma.sync.aligned.m16n8k16.row.col.f32.bf16.bf16.f32 "
        "{%0,%1,%2,%3}, {%4,%5,%6,%7}, {%8,%9}, {%0,%1,%2,%3};"
        : "+f"(c[0]), "+f"(c[1]), "+f"(c[2]), "+f"(c[3])
        : "r"(a[0]), "r"(a[1]), "r"(a[2]), "r"(a[3]), "r"(b0), "r"(b1));
}
__device__ __forceinline__ uint32_t sw_off(int row, int ch) {
    return ((uint32_t)row << 6) + (((ch ^ (row >> 1)) & 3) << 4);
}

// ---------------- stats pass 1 (fused with x split) ----------------
// 4096 blocks x 256 threads; each thread handles exactly one float4.
__global__ __launch_bounds__(256)
void stat_split(const float* __restrict__ xp,
                __nv_bfloat16* __restrict__ hi,
                __nv_bfloat16* __restrict__ lo) {
    const int i = blockIdx.x * blockDim.x + threadIdx.x;
    float4 v = ((const float4*)xp)[i];

    // split write
    __nv_bfloat16 h0 = __float2bfloat16(v.x);
    __nv_bfloat16 h1 = __float2bfloat16(v.y);
    __nv_bfloat16 h2 = __float2bfloat16(v.z);
    __nv_bfloat16 h3 = __float2bfloat16(v.w);
    __nv_bfloat16 l0 = __float2bfloat16(v.x - __bfloat162float(h0));
    __nv_bfloat16 l1 = __float2bfloat16(v.y - __bfloat162float(h1));
    __nv_bfloat16 l2 = __float2bfloat16(v.z - __bfloat162float(h2));
    __nv_bfloat16 l3 = __float2bfloat16(v.w - __bfloat162float(h3));
    __nv_bfloat162 hp0 = {h0, h1}, hp1 = {h2, h3};
    __nv_bfloat162 lp0 = {l0, l1}, lp1 = {l2, l3};
    uint2 hv = {*(uint32_t*)&hp0, *(uint32_t*)&hp1};
    uint2 lv = {*(uint32_t*)&lp0, *(uint32_t*)&lp1};
    ((uint2*)hi)[i] = hv;
    ((uint2*)lo)[i] = lv;

    // zero colsum accumulator (block 0 only; consumers launch later in-stream)
    if (blockIdx.x == 0) {
#pragma unroll
        for (int c = 0; c < HID / 256; c++)
            g_colsum[threadIdx.x + c * 256] = 0.f;
    }

    // partial sums
    float s = v.x + v.y + v.z + v.w;
    float ss = v.x * v.x + v.y * v.y + v.z * v.z + v.w * v.w;
    __shared__ float shs[256];
    __shared__ float shss[256];
    int tid = threadIdx.x;
    shs[tid] = s; shss[tid] = ss;
    __syncthreads();
    for (int o = 128; o > 0; o >>= 1) {
        if (tid < o) { shs[tid] += shs[tid + o]; shss[tid] += shss[tid + o]; }
        __syncthreads();
    }
    if (tid == 0) { g_part_s[blockIdx.x] = shs[0]; g_part_ss[blockIdx.x] = shss[0]; }
}

__global__ void stat_pass2(int nblocks, int n) {
    __shared__ float shs[1024];
    __shared__ float shss[1024];
    int tid = threadIdx.x;
    float s = 0.f, ss = 0.f;
    for (int i = tid; i < nblocks; i += 1024) { s += g_part_s[i]; ss += g_part_ss[i]; }
    shs[tid] = s; shss[tid] = ss;
    __syncthreads();
    for (int o = 512; o > 0; o >>= 1) {
        if (tid < o) { shs[tid] += shs[tid + o]; shss[tid] += shss[tid + o]; }
        __syncthreads();
    }
    if (tid == 0) {
        float S = shs[0], SS = shss[0];
        float mean = S / (float)n;
        float var = (SS - S * mean) / (float)(n - 1);
        g_stats[0] = mean;
        g_stats[1] = rsqrtf(var);
    }
}

// ---------------- transpose + split (optionally accumulate column sums) ----------------
template <int DOCOLSUM>
__global__ __launch_bounds__(256)
void transpose_split(const float* __restrict__ src,
                     __nv_bfloat16* __restrict__ dhi,
                     __nv_bfloat16* __restrict__ dlo, int K, int N) {
    __shared__ float t[32][33];
    const int n0 = blockIdx.x * 32;
    const int k0 = blockIdx.y * 32;
    const int tx = threadIdx.x & 31;
    const int ty = threadIdx.x >> 5;
#pragma unroll
    for (int i = 0; i < 32; i += 8)
        t[ty + i][tx] = src[(size_t)(k0 + ty + i) * N + n0 + tx];
    __syncthreads();
    if (DOCOLSUM && threadIdx.x < 32) {
        float s = 0.f;
#pragma unroll
        for (int r = 0; r < 32; r++) s += t[r][threadIdx.x];
        atomicAdd(&g_colsum[n0 + threadIdx.x], s);
    }
#pragma unroll
    for (int i = 0; i < 32; i += 8) {
        float v = t[tx][ty + i];
        __nv_bfloat16 h = __float2bfloat16(v);
        __nv_bfloat16 l = __float2bfloat16(v - __bfloat162float(h));
        size_t o = (size_t)(n0 + ty + i) * K + k0 + tx;
        dhi[o] = h;
        dlo[o] = l;
    }
}

// ---------------- bf16 3-split GEMM (2 CTAs/SM target) ----------------
template <int EPI>
__global__ __launch_bounds__(256, 2)
void gemm_bf16(const __nv_bfloat16* __restrict__ Ahi,
               const __nv_bfloat16* __restrict__ Alo,
               const __nv_bfloat16* __restrict__ Bhi,
               const __nv_bfloat16* __restrict__ Blo,
               const float* __restrict__ bias,
               const float* __restrict__ colsum,
               float* __restrict__ Cf,
               __nv_bfloat16* __restrict__ Chi,
               __nv_bfloat16* __restrict__ Clo,
               int K, int Nout, int KTILES) {
    extern __shared__ __align__(128) char smem[];
    const uint32_t sb = smem_u32(smem);
    const int tid = threadIdx.x;
    const int wid = tid >> 5;
    const int lane = tid & 31;
    const int wm = wid & 3;
    const int wn = wid >> 2;
    const int m0 = blockIdx.x * GBM;
    const int n0 = blockIdx.y * GBN;

    const int r0c = tid >> 2, c0c = tid & 3;
    const int r1c = (tid + 256) >> 2;

    float acc[2][8][4];
#pragma unroll
    for (int a = 0; a < 2; a++)
#pragma unroll
        for (int b = 0; b < 8; b++)
#pragma unroll
            for (int c = 0; c < 4; c++) acc[a][b][c] = 0.f;

    auto load_stage = [&](int s, int kt) {
        const uint32_t base = sb + s * STAGE_B;
        const size_t kof = (size_t)kt * GBK;
        {
            uint32_t so = sw_off(r0c, c0c);
            size_t ga = (size_t)(m0 + r0c) * K + kof + c0c * 8;
            size_t gb = (size_t)(n0 + r0c) * K + kof + c0c * 8;
            cp_async16(base + 0 * TILE_B + so, Ahi + ga);
            cp_async16(base + 1 * TILE_B + so, Alo + ga);
            cp_async16(base + 2 * TILE_B + so, Bhi + gb);
            cp_async16(base + 3 * TILE_B + so, Blo + gb);
        }
        {
            uint32_t so = sw_off(r1c, c0c);
            size_t ga = (size_t)(m0 + r1c) * K + kof + c0c * 8;
            size_t gb = (size_t)(n0 + r1c) * K + kof + c0c * 8;
            cp_async16(base + 0 * TILE_B + so, Ahi + ga);
            cp_async16(base + 1 * TILE_B + so, Alo + ga);
            cp_async16(base + 2 * TILE_B + so, Bhi + gb);
            cp_async16(base + 3 * TILE_B + so, Blo + gb);
        }
    };

    // prologue: fill GSTAGES-1 stages
#pragma unroll
    for (int s = 0; s < GSTAGES - 1; s++) {
        load_stage(s, s);
        cp_commit();
    }

    const int lrow = lane & 15;
    const int lhalf = lane >> 4;

    int cs = 0;                    // compute stage
    int ls = GSTAGES - 1;          // next load stage
    for (int kt = 0; kt < KTILES; kt++) {
        cp_wait<GSTAGES - 2>();
        __syncthreads();

        const uint32_t sAhi = sb + cs * STAGE_B;
        const uint32_t sAlo = sAhi + TILE_B;
        const uint32_t sBhi = sAhi + 2 * TILE_B;
        const uint32_t sBlo = sAhi + 3 * TILE_B;

#pragma unroll
        for (int k16 = 0; k16 < 2; k16++) {
            const int kc = k16 * 2 + lhalf;
            uint32_t ahi[2][4], alo[2][4];
#pragma unroll
            for (int mt = 0; mt < 2; mt++) {
                int row = wm * 32 + mt * 16 + lrow;
                uint32_t off = sw_off(row, kc);
                ldmatrix_x4(ahi[mt], sAhi + off);
                ldmatrix_x4(alo[mt], sAlo + off);
            }
#pragma unroll
            for (int g = 0; g < 4; g++) {
                int row = wn * 64 + g * 16 + lrow;
                uint32_t off = sw_off(row, kc);
                uint32_t bh[4], bl[4];
                ldmatrix_x4(bh, sBhi + off);
                ldmatrix_x4(bl, sBlo + off);
#pragma unroll
                for (int mt = 0; mt < 2; mt++) {
#pragma unroll
                    for (int p = 0; p < 2; p++) {
                        float* c = acc[mt][g * 2 + p];
                        mma16816(c, ahi[mt], bh[p], bh[2 + p]);
                        mma16816(c, ahi[mt], bl[p], bl[2 + p]);
                        mma16816(c, alo[mt], bh[p], bh[2 + p]);
                    }
                }
            }
        }
        __syncthreads();
        const int nk = kt + GSTAGES - 1;
        if (nk < KTILES) load_stage(ls, nk);
        cp_commit();
        cs = (cs + 1 == GSTAGES) ? 0 : cs + 1;
        ls = (ls + 1 == GSTAGES) ? 0 : ls + 1;
    }

    // ---------------- epilogue ----------------
    float mean = 0.f, invstd = 1.f;
    if (EPI == 0) { mean = g_stats[0]; invstd = g_stats[1]; }

    const int r_base = m0 + wm * 32 + (lane >> 2);
    const int c_base = n0 + wn * 64 + (lane & 3) * 2;

#pragma unroll
    for (int mt = 0; mt < 2; mt++) {
#pragma unroll
        for (int nf = 0; nf < 8; nf++) {
            const int col = c_base + nf * 8;
            float be0, be1;
            if (EPI == 0) {
                be0 = bias[col]     - mean * invstd * colsum[col];
                be1 = bias[col + 1] - mean * invstd * colsum[col + 1];
            } else {
                be0 = bias[col];
                be1 = bias[col + 1];
            }
#pragma unroll
            for (int hh = 0; hh < 2; hh++) {
                const int row = r_base + mt * 16 + hh * 8;
                float v0 = acc[mt][nf][hh * 2 + 0];
                float v1 = acc[mt][nf][hh * 2 + 1];
                if (EPI == 0) {
                    v0 = tanhf(fmaf(invstd, v0, be0));
                    v1 = tanhf(fmaf(invstd, v1, be1));
                    __nv_bfloat16 h0 = __float2bfloat16(v0);
                    __nv_bfloat16 h1 = __float2bfloat16(v1);
                    __nv_bfloat16 l0 = __float2bfloat16(v0 - __bfloat162float(h0));
                    __nv_bfloat16 l1 = __float2bfloat16(v1 - __bfloat162float(h1));
                    __nv_bfloat162 hp = {h0, h1};
                    __nv_bfloat162 lp = {l0, l1};
                    *(__nv_bfloat162*)(Chi + (size_t)row * Nout + col) = hp;
                    *(__nv_bfloat162*)(Clo + (size_t)row * Nout + col) = lp;
                } else {
                    float2 o;
                    o.x = tanhf(v0 + be0);
                    o.y = tanhf(v1 + be1);
                    *(float2*)(Cf + (size_t)row * Nout + col) = o;
                }
            }
        }
    }
}

// ---------------- spline evaluation + per-row log reduction ----------------
__global__ __launch_bounds__(256)
void spline_kernel(const float* __restrict__ net, const float* __restrict__ x_in,
                   const float* __restrict__ logd, float* __restrict__ phi_out,
                   float* __restrict__ log_out) {
    const int b = blockIdx.x;
    const int tid = threadIdx.x;
    const float* row = net + (size_t)b * OUTW;

    __shared__ float sh[256 * NC];
    __shared__ float red[256];

    float lsum = 0.f;

    for (int chunk = 0; chunk < 8; chunk++) {
        __syncthreads();
        for (int i = tid; i < 256 * NC; i += 256)
            sh[i] = row[chunk * 256 * NC + i];
        __syncthreads();

        const int s = chunk * 256 + tid;
        const float* p = sh + tid * NC;

        float hr[9], wr[8];
#pragma unroll
        for (int c = 0; c < 9; c++) hr[c] = p[c];
#pragma unroll
        for (int c = 0; c < 8; c++) wr[c] = p[9 + c];

        float m = wr[0];
#pragma unroll
        for (int c = 1; c < 8; c++) m = fmaxf(m, wr[c]);
        float wn[8];
        float wsum = 0.f;
#pragma unroll
        for (int c = 0; c < 8; c++) { wn[c] = expf(wr[c] - m); wsum += wn[c]; }
        float winv = 1.0f / wsum;
#pragma unroll
        for (int c = 0; c < 8; c++) wn[c] *= winv;

        float eh[9];
#pragma unroll
        for (int c = 0; c < 9; c++) eh[c] = expf(hr[c]);
        float denom = 0.f;
#pragma unroll
        for (int c = 0; c < 8; c++) denom += 0.5f * wn[c] * (eh[c] + eh[c + 1]);
        float dinv = 1.0f / denom;
        float hn[9];
#pragma unroll
        for (int c = 0; c < 9; c++) hn[c] = eh[c] * dinv;

        const float x = x_in[(size_t)b * SIZE_D + s] * 0.31830988618379067154f;

        float cum = 0.f, phicum = 0.f;
        float wk = wn[0], hk = hn[0], hk1 = hn[1];
        float xkm1 = -EPS_C, phikm1 = 0.f;
#pragma unroll
        for (int i = 0; i < 7; i++) {
            float trap = 0.5f * wn[i] * (hn[i] + hn[i + 1]);
            cum += wn[i];
            phicum += trap;
            bool c = (cum < x);
            wk     = c ? wn[i + 1] : wk;
            hk     = c ? hn[i + 1] : hk;
            hk1    = c ? hn[i + 2] : hk1;
            xkm1   = c ? cum      : xkm1;
            phikm1 = c ? phicum   : phikm1;
        }

        float alpha = (x - xkm1) / wk;
        float phi = phikm1 + alpha * hk * wk
                  + 0.5f * alpha * alpha * (hk1 - hk) * wk;
        phi_out[(size_t)b * SIZE_D + s] = phi;
        lsum += logf(hk + alpha * (hk1 - hk));
    }

    red[tid] = lsum;
    __syncthreads();
    for (int o = 128; o > 0; o >>= 1) {
        if (tid < o) red[tid] += red[tid + o];
        __syncthreads();
    }
    if (tid == 0) log_out[b] = logd[b] - red[0];
}

// ---------------- launch ----------------
extern "C" void kernel_launch(void* const* d_in, const int* in_sizes, int n_in,
                              void* d_out, int out_size) {
    (void)in_sizes; (void)n_in; (void)out_size;
    const float* x_in      = (const float*)d_in[0];
    const float* x_passive = (const float*)d_in[1];
    const float* log_dens  = (const float*)d_in[2];
    const float* w1        = (const float*)d_in[3];
    const float* b1        = (const float*)d_in[4];
    const float* w2        = (const float*)d_in[5];
    const float* b2        = (const float*)d_in[6];

    float* out_phi = (float*)d_out;
    float* out_log = (float*)d_out + (size_t)NTOT;

    __nv_bfloat16 *xhi, *xlo, *w1thi, *w1tlo, *hhi, *hlo, *w2thi, *w2tlo;
    float *nbuf, *csum;
    cudaGetSymbolAddress((void**)&xhi, g_xhi);
    cudaGetSymbolAddress((void**)&xlo, g_xlo);
    cudaGetSymbolAddress((void**)&w1thi, g_w1t_hi);
    cudaGetSymbolAddress((void**)&w1tlo, g_w1t_lo);
    cudaGetSymbolAddress((void**)&hhi, g_hhi);
    cudaGetSymbolAddress((void**)&hlo, g_hlo);
    cudaGetSymbolAddress((void**)&w2thi, g_w2t_hi);
    cudaGetSymbolAddress((void**)&w2tlo, g_w2t_lo);
    cudaGetSymbolAddress((void**)&nbuf, g_net);
    cudaGetSymbolAddress((void**)&csum, g_colsum);

    cudaFuncSetAttribute(gemm_bf16<0>, cudaFuncAttributeMaxDynamicSharedMemorySize,
                         GEMM_SMEM);
    cudaFuncSetAttribute(gemm_bf16<1>, cudaFuncAttributeMaxDynamicSharedMemorySize,
                         GEMM_SMEM);

    // 0) stats partials + x split + colsum zero (fused)
    stat_split<<<NSTATBLK, 256>>>(x_passive, xhi, xlo);
    // 1) stats finalize
    stat_pass2<<<1, 1024>>>(NSTATBLK, NTOT);
    // 2) w1 transpose/split + colsum accumulate
    transpose_split<1><<<dim3(HID / 32, SIZE_D / 32), 256>>>(w1, w1thi, w1tlo,
                                                             SIZE_D, HID);
    // 3) w2 transpose/split
    transpose_split<0><<<dim3(OUTW / 32, HID / 32), 256>>>(w2, w2thi, w2tlo,
                                                           HID, OUTW);
    // 4) GEMM1: h = tanh(xs @ w1 + b1) -> bf16 hi/lo
    gemm_bf16<0><<<dim3(BATCH / GBM, HID / GBN), 256, GEMM_SMEM>>>(
        xhi, xlo, w1thi, w1tlo, b1, csum,
        nullptr, hhi, hlo, SIZE_D, HID, SIZE_D / GBK);
    // 5) GEMM2: net = tanh(h @ w2 + b2) -> fp32
    gemm_bf16<1><<<dim3(BATCH / GBM, OUTW / GBN), 256, GEMM_SMEM>>>(
        hhi, hlo, w2thi, w2tlo, b2, nullptr,
        nbuf, nullptr, nullptr, HID, OUTW, HID / GBK);
    // 6) spline + per-row log-density reduction
    spline_kernel<<<BATCH, 256>>>(nbuf, x_in, log_dens, out_phi, out_log);
}

// round 7
// speedup vs baseline: 3.8787x; 1.3423x over previous
#include <cuda_runtime.h>
#include <cuda_fp16.h>
#include <math.h>
#include <stdint.h>

// ---------------- problem constants ----------------
#define BATCH 2048
#define SIZE_D 2048
#define HID 1024
#define NC 17
#define OUTW (SIZE_D * NC)   // 34816
#define NTOT (BATCH * SIZE_D)
#define EPS_C 1e-6f
#define NSTATBLK (NTOT / 4 / 256)   // 4096

// ---------------- GEMM tiling ----------------
#define GBM 128
#define GBN 128
#define GBK 32
#define GSTAGES 4
#define TILE_B (GBM * 64)        // 128 rows x 32 fp16 (64B/row) = 8192B
#define STAGE_B (3 * TILE_B)     // A, Bhi, Blo = 24576B
#define GEMM_SMEM (GSTAGES * STAGE_B)  // 98304 -> 2 CTAs/SM

// ---------------- device scratch (allocation-free rule) ----------------
__device__ __half g_xh[(size_t)NTOT];                 // x_passive fp16
__device__ __half g_w1t_hi[(size_t)HID * SIZE_D];     // [1024][2048]
__device__ __half g_w1t_lo[(size_t)HID * SIZE_D];
__device__ __half g_h[(size_t)BATCH * HID];           // h fp16 (A of GEMM2)
__device__ __half g_w2t_hi[(size_t)OUTW * HID];       // [34816][1024]
__device__ __half g_w2t_lo[(size_t)OUTW * HID];
__device__ float g_net[(size_t)BATCH * OUTW];
__device__ float g_colsum[HID];
__device__ float g_part_s[NSTATBLK];
__device__ float g_part_ss[NSTATBLK];
__device__ float g_stats[2];

// ---------------- PTX helpers ----------------
__device__ __forceinline__ uint32_t smem_u32(const void* p) {
    uint32_t a;
    asm("{ .reg .u64 t; cvta.to.shared.u64 t, %1; cvt.u32.u64 %0, t; }"
        : "=r"(a) : "l"(p));
    return a;
}
__device__ __forceinline__ void cp_async16(uint32_t sa, const void* ga) {
    asm volatile("cp.async.cg.shared.global [%0], [%1], 16;"
                 :: "r"(sa), "l"(ga) : "memory");
}
__device__ __forceinline__ void cp_commit() {
    asm volatile("cp.async.commit_group;" ::: "memory");
}
template <int N>
__device__ __forceinline__ void cp_wait() {
    asm volatile("cp.async.wait_group %0;" :: "n"(N) : "memory");
}
__device__ __forceinline__ void ldmatrix_x4(uint32_t* r, uint32_t addr) {
    asm volatile("ldmatrix.sync.aligned.m8n8.x4.shared.b16 {%0,%1,%2,%3}, [%4];"
                 : "=r"(r[0]), "=r"(r[1]), "=r"(r[2]), "=r"(r[3])
                 : "r"(addr));
}
__device__ __forceinline__ void mma16816(float* c, const uint32_t* a,
                                         uint32_t b0, uint32_t b1) {
    asm volatile(
        "mma.sync.aligned.m16n8k16.row.col.f32.f16.f16.f32 "
        "{%0,%1,%2,%3}, {%4,%5,%6,%7}, {%8,%9}, {%0,%1,%2,%3};"
        : "+f"(c[0]), "+f"(c[1]), "+f"(c[2]), "+f"(c[3])
        : "r"(a[0]), "r"(a[1]), "r"(a[2]), "r"(a[3]), "r"(b0), "r"(b1));
}
__device__ __forceinline__ uint32_t sw_off(int row, int ch) {
    return ((uint32_t)row << 6) + (((ch ^ (row >> 1)) & 3) << 4);
}

// ---------------- stats pass 1 (fused with x fp16 convert) ----------------
// 4096 blocks x 256 threads; each thread handles one float4.
__global__ __launch_bounds__(256)
void stat_split(const float* __restrict__ xp, __half* __restrict__ xh) {
    const int i = blockIdx.x * blockDim.x + threadIdx.x;
    float4 v = ((const float4*)xp)[i];

    __half2 p0 = {__float2half_rn(v.x), __float2half_rn(v.y)};
    __half2 p1 = {__float2half_rn(v.z), __float2half_rn(v.w)};
    uint2 hv = {*(uint32_t*)&p0, *(uint32_t*)&p1};
    ((uint2*)xh)[i] = hv;

    if (blockIdx.x == 0) {
#pragma unroll
        for (int c = 0; c < HID / 256; c++)
            g_colsum[threadIdx.x + c * 256] = 0.f;
    }

    float s = v.x + v.y + v.z + v.w;
    float ss = v.x * v.x + v.y * v.y + v.z * v.z + v.w * v.w;
    __shared__ float shs[256];
    __shared__ float shss[256];
    int tid = threadIdx.x;
    shs[tid] = s; shss[tid] = ss;
    __syncthreads();
    for (int o = 128; o > 0; o >>= 1) {
        if (tid < o) { shs[tid] += shs[tid + o]; shss[tid] += shss[tid + o]; }
        __syncthreads();
    }
    if (tid == 0) { g_part_s[blockIdx.x] = shs[0]; g_part_ss[blockIdx.x] = shss[0]; }
}

__global__ void stat_pass2(int nblocks, int n) {
    __shared__ float shs[1024];
    __shared__ float shss[1024];
    int tid = threadIdx.x;
    float s = 0.f, ss = 0.f;
    for (int i = tid; i < nblocks; i += 1024) { s += g_part_s[i]; ss += g_part_ss[i]; }
    shs[tid] = s; shss[tid] = ss;
    __syncthreads();
    for (int o = 512; o > 0; o >>= 1) {
        if (tid < o) { shs[tid] += shs[tid + o]; shss[tid] += shss[tid + o]; }
        __syncthreads();
    }
    if (tid == 0) {
        float S = shs[0], SS = shss[0];
        float mean = S / (float)n;
        float var = (SS - S * mean) / (float)(n - 1);
        g_stats[0] = mean;
        g_stats[1] = rsqrtf(var);
    }
}

// ---------------- transpose + fp16 split (optional column sums) ----------------
// src [K][N] fp32 -> dst hi/lo [N][K] fp16
template <int DOCOLSUM>
__global__ __launch_bounds__(256)
void transpose_split(const float* __restrict__ src,
                     __half* __restrict__ dhi,
                     __half* __restrict__ dlo, int K, int N) {
    __shared__ float t[32][33];
    const int n0 = blockIdx.x * 32;
    const int k0 = blockIdx.y * 32;
    const int tx = threadIdx.x & 31;
    const int ty = threadIdx.x >> 5;
#pragma unroll
    for (int i = 0; i < 32; i += 8)
        t[ty + i][tx] = src[(size_t)(k0 + ty + i) * N + n0 + tx];
    __syncthreads();
    if (DOCOLSUM && threadIdx.x < 32) {
        float s = 0.f;
#pragma unroll
        for (int r = 0; r < 32; r++) s += t[r][threadIdx.x];
        atomicAdd(&g_colsum[n0 + threadIdx.x], s);
    }
#pragma unroll
    for (int i = 0; i < 32; i += 8) {
        float v = t[tx][ty + i];
        __half h = __float2half_rn(v);
        __half l = __float2half_rn(v - __half2float(h));
        size_t o = (size_t)(n0 + ty + i) * K + k0 + tx;
        dhi[o] = h;
        dlo[o] = l;
    }
}

// ---------------- fp16 2-term GEMM ----------------
// C = tanh(scale * (A @ (Bhi+Blo)^T) + bias_eff)
//   EPI==0: scale=invstd, bias_eff=b1-mean*invstd*colsum -> fp16 out (Chalf)
//   EPI==1: scale=1, bias_eff=bias                        -> fp32 out (Cf)
template <int EPI>
__global__ __launch_bounds__(256, 2)
void gemm_fp16(const __half* __restrict__ A,
               const __half* __restrict__ Bhi,
               const __half* __restrict__ Blo,
               const float* __restrict__ bias,
               const float* __restrict__ colsum,
               float* __restrict__ Cf,
               __half* __restrict__ Chalf,
               int K, int Nout, int KTILES) {
    extern __shared__ __align__(128) char smem[];
    const uint32_t sb = smem_u32(smem);
    const int tid = threadIdx.x;
    const int wid = tid >> 5;
    const int lane = tid & 31;
    const int wm = wid & 3;
    const int wn = wid >> 2;
    const int m0 = blockIdx.x * GBM;
    const int n0 = blockIdx.y * GBN;

    const int r0c = tid >> 2, c0c = tid & 3;
    const int r1c = (tid + 256) >> 2;

    float acc[2][8][4];
#pragma unroll
    for (int a = 0; a < 2; a++)
#pragma unroll
        for (int b = 0; b < 8; b++)
#pragma unroll
            for (int c = 0; c < 4; c++) acc[a][b][c] = 0.f;

    auto load_stage = [&](int s, int kt) {
        const uint32_t base = sb + s * STAGE_B;
        const size_t kof = (size_t)kt * GBK;
        {
            uint32_t so = sw_off(r0c, c0c);
            size_t ga = (size_t)(m0 + r0c) * K + kof + c0c * 8;
            size_t gb = (size_t)(n0 + r0c) * K + kof + c0c * 8;
            cp_async16(base + 0 * TILE_B + so, A + ga);
            cp_async16(base + 1 * TILE_B + so, Bhi + gb);
            cp_async16(base + 2 * TILE_B + so, Blo + gb);
        }
        {
            uint32_t so = sw_off(r1c, c0c);
            size_t ga = (size_t)(m0 + r1c) * K + kof + c0c * 8;
            size_t gb = (size_t)(n0 + r1c) * K + kof + c0c * 8;
            cp_async16(base + 0 * TILE_B + so, A + ga);
            cp_async16(base + 1 * TILE_B + so, Bhi + gb);
            cp_async16(base + 2 * TILE_B + so, Blo + gb);
        }
    };

#pragma unroll
    for (int s = 0; s < GSTAGES - 1; s++) {
        load_stage(s, s);
        cp_commit();
    }

    const int lrow = lane & 15;
    const int lhalf = lane >> 4;

    int cs = 0;
    int ls = GSTAGES - 1;
    for (int kt = 0; kt < KTILES; kt++) {
        cp_wait<GSTAGES - 2>();
        __syncthreads();

        const uint32_t sA   = sb + cs * STAGE_B;
        const uint32_t sBhi = sA + TILE_B;
        const uint32_t sBlo = sA + 2 * TILE_B;

#pragma unroll
        for (int k16 = 0; k16 < 2; k16++) {
            const int kc = k16 * 2 + lhalf;
            uint32_t afr[2][4];
#pragma unroll
            for (int mt = 0; mt < 2; mt++) {
                int row = wm * 32 + mt * 16 + lrow;
                ldmatrix_x4(afr[mt], sA + sw_off(row, kc));
            }
#pragma unroll
            for (int g = 0; g < 4; g++) {
                int row = wn * 64 + g * 16 + lrow;
                uint32_t off = sw_off(row, kc);
                uint32_t bh[4], bl[4];
                ldmatrix_x4(bh, sBhi + off);
                ldmatrix_x4(bl, sBlo + off);
#pragma unroll
                for (int mt = 0; mt < 2; mt++) {
#pragma unroll
                    for (int p = 0; p < 2; p++) {
                        float* c = acc[mt][g * 2 + p];
                        mma16816(c, afr[mt], bh[p], bh[2 + p]);
                        mma16816(c, afr[mt], bl[p], bl[2 + p]);
                    }
                }
            }
        }
        __syncthreads();
        const int nk = kt + GSTAGES - 1;
        if (nk < KTILES) load_stage(ls, nk);
        cp_commit();
        cs = (cs + 1 == GSTAGES) ? 0 : cs + 1;
        ls = (ls + 1 == GSTAGES) ? 0 : ls + 1;
    }

    // ---------------- epilogue ----------------
    float mean = 0.f, invstd = 1.f;
    if (EPI == 0) { mean = g_stats[0]; invstd = g_stats[1]; }

    const int r_base = m0 + wm * 32 + (lane >> 2);
    const int c_base = n0 + wn * 64 + (lane & 3) * 2;

#pragma unroll
    for (int mt = 0; mt < 2; mt++) {
#pragma unroll
        for (int nf = 0; nf < 8; nf++) {
            const int col = c_base + nf * 8;
            float be0, be1;
            if (EPI == 0) {
                be0 = bias[col]     - mean * invstd * colsum[col];
                be1 = bias[col + 1] - mean * invstd * colsum[col + 1];
            } else {
                be0 = bias[col];
                be1 = bias[col + 1];
            }
#pragma unroll
            for (int hh = 0; hh < 2; hh++) {
                const int row = r_base + mt * 16 + hh * 8;
                float v0 = acc[mt][nf][hh * 2 + 0];
                float v1 = acc[mt][nf][hh * 2 + 1];
                if (EPI == 0) {
                    v0 = tanhf(fmaf(invstd, v0, be0));
                    v1 = tanhf(fmaf(invstd, v1, be1));
                    __half2 hp = {__float2half_rn(v0), __float2half_rn(v1)};
                    *(__half2*)(Chalf + (size_t)row * Nout + col) = hp;
                } else {
                    float2 o;
                    o.x = tanhf(v0 + be0);
                    o.y = tanhf(v1 + be1);
                    *(float2*)(Cf + (size_t)row * Nout + col) = o;
                }
            }
        }
    }
}

// ---------------- spline evaluation + per-row log reduction ----------------
__global__ __launch_bounds__(256)
void spline_kernel(const float* __restrict__ net, const float* __restrict__ x_in,
                   const float* __restrict__ logd, float* __restrict__ phi_out,
                   float* __restrict__ log_out) {
    const int b = blockIdx.x;
    const int tid = threadIdx.x;
    const float* row = net + (size_t)b * OUTW;

    __shared__ float sh[256 * NC];
    __shared__ float red[256];

    float lsum = 0.f;

    for (int chunk = 0; chunk < 8; chunk++) {
        __syncthreads();
        for (int i = tid; i < 256 * NC; i += 256)
            sh[i] = row[chunk * 256 * NC + i];
        __syncthreads();

        const int s = chunk * 256 + tid;
        const float* p = sh + tid * NC;

        float hr[9], wr[8];
#pragma unroll
        for (int c = 0; c < 9; c++) hr[c] = p[c];
#pragma unroll
        for (int c = 0; c < 8; c++) wr[c] = p[9 + c];

        float m = wr[0];
#pragma unroll
        for (int c = 1; c < 8; c++) m = fmaxf(m, wr[c]);
        float wn[8];
        float wsum = 0.f;
#pragma unroll
        for (int c = 0; c < 8; c++) { wn[c] = expf(wr[c] - m); wsum += wn[c]; }
        float winv = 1.0f / wsum;
#pragma unroll
        for (int c = 0; c < 8; c++) wn[c] *= winv;

        float eh[9];
#pragma unroll
        for (int c = 0; c < 9; c++) eh[c] = expf(hr[c]);
        float denom = 0.f;
#pragma unroll
        for (int c = 0; c < 8; c++) denom += 0.5f * wn[c] * (eh[c] + eh[c + 1]);
        float dinv = 1.0f / denom;
        float hn[9];
#pragma unroll
        for (int c = 0; c < 9; c++) hn[c] = eh[c] * dinv;

        const float x = x_in[(size_t)b * SIZE_D + s] * 0.31830988618379067154f;

        float cum = 0.f, phicum = 0.f;
        float wk = wn[0], hk = hn[0], hk1 = hn[1];
        float xkm1 = -EPS_C, phikm1 = 0.f;
#pragma unroll
        for (int i = 0; i < 7; i++) {
            float trap = 0.5f * wn[i] * (hn[i] + hn[i + 1]);
            cum += wn[i];
            phicum += trap;
            bool c = (cum < x);
            wk     = c ? wn[i + 1] : wk;
            hk     = c ? hn[i + 1] : hk;
            hk1    = c ? hn[i + 2] : hk1;
            xkm1   = c ? cum      : xkm1;
            phikm1 = c ? phicum   : phikm1;
        }

        float alpha = (x - xkm1) / wk;
        float phi = phikm1 + alpha * hk * wk
                  + 0.5f * alpha * alpha * (hk1 - hk) * wk;
        phi_out[(size_t)b * SIZE_D + s] = phi;
        lsum += logf(hk + alpha * (hk1 - hk));
    }

    red[tid] = lsum;
    __syncthreads();
    for (int o = 128; o > 0; o >>= 1) {
        if (tid < o) red[tid] += red[tid + o];
        __syncthreads();
    }
    if (tid == 0) log_out[b] = logd[b] - red[0];
}

// ---------------- launch ----------------
extern "C" void kernel_launch(void* const* d_in, const int* in_sizes, int n_in,
                              void* d_out, int out_size) {
    (void)in_sizes; (void)n_in; (void)out_size;
    const float* x_in      = (const float*)d_in[0];
    const float* x_passive = (const float*)d_in[1];
    const float* log_dens  = (const float*)d_in[2];
    const float* w1        = (const float*)d_in[3];
    const float* b1        = (const float*)d_in[4];
    const float* w2        = (const float*)d_in[5];
    const float* b2        = (const float*)d_in[6];

    float* out_phi = (float*)d_out;
    float* out_log = (float*)d_out + (size_t)NTOT;

    __half *xh, *w1thi, *w1tlo, *hbuf, *w2thi, *w2tlo;
    float *nbuf, *csum;
    cudaGetSymbolAddress((void**)&xh, g_xh);
    cudaGetSymbolAddress((void**)&w1thi, g_w1t_hi);
    cudaGetSymbolAddress((void**)&w1tlo, g_w1t_lo);
    cudaGetSymbolAddress((void**)&hbuf, g_h);
    cudaGetSymbolAddress((void**)&w2thi, g_w2t_hi);
    cudaGetSymbolAddress((void**)&w2tlo, g_w2t_lo);
    cudaGetSymbolAddress((void**)&nbuf, g_net);
    cudaGetSymbolAddress((void**)&csum, g_colsum);

    cudaFuncSetAttribute(gemm_fp16<0>, cudaFuncAttributeMaxDynamicSharedMemorySize,
                         GEMM_SMEM);
    cudaFuncSetAttribute(gemm_fp16<1>, cudaFuncAttributeMaxDynamicSharedMemorySize,
                         GEMM_SMEM);

    // 0) stats partials + x fp16 convert + colsum zero (fused)
    stat_split<<<NSTATBLK, 256>>>(x_passive, xh);
    // 1) stats finalize
    stat_pass2<<<1, 1024>>>(NSTATBLK, NTOT);
    // 2) w1 transpose/split + colsum accumulate
    transpose_split<1><<<dim3(HID / 32, SIZE_D / 32), 256>>>(w1, w1thi, w1tlo,
                                                             SIZE_D, HID);
    // 3) w2 transpose/split
    transpose_split<0><<<dim3(OUTW / 32, HID / 32), 256>>>(w2, w2thi, w2tlo,
                                                           HID, OUTW);
    // 4) GEMM1: h = tanh(xs @ w1 + b1) -> fp16
    gemm_fp16<0><<<dim3(BATCH / GBM, HID / GBN), 256, GEMM_SMEM>>>(
        xh, w1thi, w1tlo, b1, csum,
        nullptr, hbuf, SIZE_D, HID, SIZE_D / GBK);
    // 5) GEMM2: net = tanh(h @ w2 + b2) -> fp32
    gemm_fp16<1><<<dim3(BATCH / GBM, OUTW / GBN), 256, GEMM_SMEM>>>(
        hbuf, w2thi, w2tlo, b2, nullptr,
        nbuf, nullptr, HID, OUTW, HID / GBK);
    // 6) spline + per-row log-density reduction
    spline_kernel<<<BATCH, 256>>>(nbuf, x_in, log_dens, out_phi, out_log);
}

// round 8
// speedup vs baseline: 6.1270x; 1.5796x over previous
#include <cuda_runtime.h>
#include <cuda_fp16.h>
#include <math.h>
#include <stdint.h>

// ---------------- problem constants ----------------
#define BATCH 2048
#define SIZE_D 2048
#define HID 1024
#define NC 17
#define OUTW (SIZE_D * NC)   // 34816
#define NTOT (BATCH * SIZE_D)
#define EPS_C 1e-6f
#define NSTATBLK (NTOT / 4 / 256)   // 4096

// ---------------- GEMM tiling ----------------
#define GBM 128
#define GBN 128
#define GBK 32
#define GSTAGES 4
#define TILE_B (GBM * 64)        // 128 rows x 32 fp16 (64B/row) = 8192B
#define STAGE_B (2 * TILE_B)     // A, B = 16384B
#define GEMM_SMEM (GSTAGES * STAGE_B)  // 65536 -> 2 CTAs/SM with headroom

// ---------------- device scratch (allocation-free rule) ----------------
__device__ __half g_xh[(size_t)NTOT];                 // x_passive fp16
__device__ __half g_w1t[(size_t)HID * SIZE_D];        // [1024][2048] fp16
__device__ __half g_h[(size_t)BATCH * HID];           // h fp16 (A of GEMM2)
__device__ __half g_w2t[(size_t)OUTW * HID];          // [34816][1024] fp16
__device__ float g_net[(size_t)BATCH * OUTW];
__device__ float g_colsum[HID];
__device__ float g_part_s[NSTATBLK];
__device__ float g_part_ss[NSTATBLK];
__device__ float g_stats[2];

// ---------------- PTX helpers ----------------
__device__ __forceinline__ uint32_t smem_u32(const void* p) {
    uint32_t a;
    asm("{ .reg .u64 t; cvta.to.shared.u64 t, %1; cvt.u32.u64 %0, t; }"
        : "=r"(a) : "l"(p));
    return a;
}
__device__ __forceinline__ void cp_async16(uint32_t sa, const void* ga) {
    asm volatile("cp.async.cg.shared.global [%0], [%1], 16;"
                 :: "r"(sa), "l"(ga) : "memory");
}
__device__ __forceinline__ void cp_commit() {
    asm volatile("cp.async.commit_group;" ::: "memory");
}
template <int N>
__device__ __forceinline__ void cp_wait() {
    asm volatile("cp.async.wait_group %0;" :: "n"(N) : "memory");
}
__device__ __forceinline__ void ldmatrix_x4(uint32_t* r, uint32_t addr) {
    asm volatile("ldmatrix.sync.aligned.m8n8.x4.shared.b16 {%0,%1,%2,%3}, [%4];"
                 : "=r"(r[0]), "=r"(r[1]), "=r"(r[2]), "=r"(r[3])
                 : "r"(addr));
}
__device__ __forceinline__ void mma16816(float* c, const uint32_t* a,
                                         uint32_t b0, uint32_t b1) {
    asm volatile(
        "mma.sync.aligned.m16n8k16.row.col.f32.f16.f16.f32 "
        "{%0,%1,%2,%3}, {%4,%5,%6,%7}, {%8,%9}, {%0,%1,%2,%3};"
        : "+f"(c[0]), "+f"(c[1]), "+f"(c[2]), "+f"(c[3])
        : "r"(a[0]), "r"(a[1]), "r"(a[2]), "r"(a[3]), "r"(b0), "r"(b1));
}
__device__ __forceinline__ uint32_t sw_off(int row, int ch) {
    return ((uint32_t)row << 6) + (((ch ^ (row >> 1)) & 3) << 4);
}

// ---------------- stats pass 1 (fused with x fp16 convert) ----------------
__global__ __launch_bounds__(256)
void stat_split(const float* __restrict__ xp, __half* __restrict__ xh) {
    const int i = blockIdx.x * blockDim.x + threadIdx.x;
    float4 v = ((const float4*)xp)[i];

    __half2 p0 = {__float2half_rn(v.x), __float2half_rn(v.y)};
    __half2 p1 = {__float2half_rn(v.z), __float2half_rn(v.w)};
    uint2 hv = {*(uint32_t*)&p0, *(uint32_t*)&p1};
    ((uint2*)xh)[i] = hv;

    if (blockIdx.x == 0) {
#pragma unroll
        for (int c = 0; c < HID / 256; c++)
            g_colsum[threadIdx.x + c * 256] = 0.f;
    }

    float s = v.x + v.y + v.z + v.w;
    float ss = v.x * v.x + v.y * v.y + v.z * v.z + v.w * v.w;
    __shared__ float shs[256];
    __shared__ float shss[256];
    int tid = threadIdx.x;
    shs[tid] = s; shss[tid] = ss;
    __syncthreads();
    for (int o = 128; o > 0; o >>= 1) {
        if (tid < o) { shs[tid] += shs[tid + o]; shss[tid] += shss[tid + o]; }
        __syncthreads();
    }
    if (tid == 0) { g_part_s[blockIdx.x] = shs[0]; g_part_ss[blockIdx.x] = shss[0]; }
}

__global__ void stat_pass2(int nblocks, int n) {
    __shared__ float shs[1024];
    __shared__ float shss[1024];
    int tid = threadIdx.x;
    float s = 0.f, ss = 0.f;
    for (int i = tid; i < nblocks; i += 1024) { s += g_part_s[i]; ss += g_part_ss[i]; }
    shs[tid] = s; shss[tid] = ss;
    __syncthreads();
    for (int o = 512; o > 0; o >>= 1) {
        if (tid < o) { shs[tid] += shs[tid + o]; shss[tid] += shss[tid + o]; }
        __syncthreads();
    }
    if (tid == 0) {
        float S = shs[0], SS = shss[0];
        float mean = S / (float)n;
        float var = (SS - S * mean) / (float)(n - 1);
        g_stats[0] = mean;
        g_stats[1] = rsqrtf(var);
    }
}

// ---------------- transpose -> fp16 (optional column sums) ----------------
// src [K][N] fp32 -> dst [N][K] fp16
template <int DOCOLSUM>
__global__ __launch_bounds__(256)
void transpose_half(const float* __restrict__ src,
                    __half* __restrict__ dst, int K, int N) {
    __shared__ float t[32][33];
    const int n0 = blockIdx.x * 32;
    const int k0 = blockIdx.y * 32;
    const int tx = threadIdx.x & 31;
    const int ty = threadIdx.x >> 5;
#pragma unroll
    for (int i = 0; i < 32; i += 8)
        t[ty + i][tx] = src[(size_t)(k0 + ty + i) * N + n0 + tx];
    __syncthreads();
    if (DOCOLSUM && threadIdx.x < 32) {
        float s = 0.f;
#pragma unroll
        for (int r = 0; r < 32; r++) s += t[r][threadIdx.x];
        atomicAdd(&g_colsum[n0 + threadIdx.x], s);
    }
#pragma unroll
    for (int i = 0; i < 32; i += 8) {
        dst[(size_t)(n0 + ty + i) * K + k0 + tx] = __float2half_rn(t[tx][ty + i]);
    }
}

// ---------------- plain fp16 GEMM (fp32 accumulate) ----------------
// C = tanh(scale * (A @ B^T) + bias_eff)
//   EPI==0: scale=invstd, bias_eff=b1-mean*invstd*colsum -> fp16 out (Chalf)
//   EPI==1: scale=1, bias_eff=bias                        -> fp32 out (Cf)
template <int EPI>
__global__ __launch_bounds__(256, 2)
void gemm_fp16(const __half* __restrict__ A,
               const __half* __restrict__ B,
               const float* __restrict__ bias,
               const float* __restrict__ colsum,
               float* __restrict__ Cf,
               __half* __restrict__ Chalf,
               int K, int Nout, int KTILES) {
    extern __shared__ __align__(128) char smem[];
    const uint32_t sb = smem_u32(smem);
    const int tid = threadIdx.x;
    const int wid = tid >> 5;
    const int lane = tid & 31;
    const int wm = wid & 3;
    const int wn = wid >> 2;
    const int m0 = blockIdx.x * GBM;
    const int n0 = blockIdx.y * GBN;

    const int r0c = tid >> 2, c0c = tid & 3;
    const int r1c = (tid + 256) >> 2;

    float acc[2][8][4];
#pragma unroll
    for (int a = 0; a < 2; a++)
#pragma unroll
        for (int b = 0; b < 8; b++)
#pragma unroll
            for (int c = 0; c < 4; c++) acc[a][b][c] = 0.f;

    auto load_stage = [&](int s, int kt) {
        const uint32_t base = sb + s * STAGE_B;
        const size_t kof = (size_t)kt * GBK;
        {
            uint32_t so = sw_off(r0c, c0c);
            size_t ga = (size_t)(m0 + r0c) * K + kof + c0c * 8;
            size_t gb = (size_t)(n0 + r0c) * K + kof + c0c * 8;
            cp_async16(base + 0 * TILE_B + so, A + ga);
            cp_async16(base + 1 * TILE_B + so, B + gb);
        }
        {
            uint32_t so = sw_off(r1c, c0c);
            size_t ga = (size_t)(m0 + r1c) * K + kof + c0c * 8;
            size_t gb = (size_t)(n0 + r1c) * K + kof + c0c * 8;
            cp_async16(base + 0 * TILE_B + so, A + ga);
            cp_async16(base + 1 * TILE_B + so, B + gb);
        }
    };

#pragma unroll
    for (int s = 0; s < GSTAGES - 1; s++) {
        load_stage(s, s);
        cp_commit();
    }

    const int lrow = lane & 15;
    const int lhalf = lane >> 4;

    int cs = 0;
    int ls = GSTAGES - 1;
    for (int kt = 0; kt < KTILES; kt++) {
        cp_wait<GSTAGES - 2>();
        __syncthreads();

        const uint32_t sA = sb + cs * STAGE_B;
        const uint32_t sB = sA + TILE_B;

#pragma unroll
        for (int k16 = 0; k16 < 2; k16++) {
            const int kc = k16 * 2 + lhalf;
            uint32_t afr[2][4];
#pragma unroll
            for (int mt = 0; mt < 2; mt++) {
                int row = wm * 32 + mt * 16 + lrow;
                ldmatrix_x4(afr[mt], sA + sw_off(row, kc));
            }
#pragma unroll
            for (int g = 0; g < 4; g++) {
                int row = wn * 64 + g * 16 + lrow;
                uint32_t bfr[4];
                ldmatrix_x4(bfr, sB + sw_off(row, kc));
#pragma unroll
                for (int mt = 0; mt < 2; mt++) {
#pragma unroll
                    for (int p = 0; p < 2; p++) {
                        mma16816(acc[mt][g * 2 + p], afr[mt], bfr[p], bfr[2 + p]);
                    }
                }
            }
        }
        __syncthreads();
        const int nk = kt + GSTAGES - 1;
        if (nk < KTILES) load_stage(ls, nk);
        cp_commit();
        cs = (cs + 1 == GSTAGES) ? 0 : cs + 1;
        ls = (ls + 1 == GSTAGES) ? 0 : ls + 1;
    }

    // ---------------- epilogue ----------------
    float mean = 0.f, invstd = 1.f;
    if (EPI == 0) { mean = g_stats[0]; invstd = g_stats[1]; }

    const int r_base = m0 + wm * 32 + (lane >> 2);
    const int c_base = n0 + wn * 64 + (lane & 3) * 2;

#pragma unroll
    for (int mt = 0; mt < 2; mt++) {
#pragma unroll
        for (int nf = 0; nf < 8; nf++) {
            const int col = c_base + nf * 8;
            float be0, be1;
            if (EPI == 0) {
                be0 = bias[col]     - mean * invstd * colsum[col];
                be1 = bias[col + 1] - mean * invstd * colsum[col + 1];
            } else {
                be0 = bias[col];
                be1 = bias[col + 1];
            }
#pragma unroll
            for (int hh = 0; hh < 2; hh++) {
                const int row = r_base + mt * 16 + hh * 8;
                float v0 = acc[mt][nf][hh * 2 + 0];
                float v1 = acc[mt][nf][hh * 2 + 1];
                if (EPI == 0) {
                    v0 = tanhf(fmaf(invstd, v0, be0));
                    v1 = tanhf(fmaf(invstd, v1, be1));
                    __half2 hp = {__float2half_rn(v0), __float2half_rn(v1)};
                    *(__half2*)(Chalf + (size_t)row * Nout + col) = hp;
                } else {
                    float2 o;
                    o.x = tanhf(v0 + be0);
                    o.y = tanhf(v1 + be1);
                    *(float2*)(Cf + (size_t)row * Nout + col) = o;
                }
            }
        }
    }
}

// ---------------- spline evaluation + per-row log reduction ----------------
__global__ __launch_bounds__(256)
void spline_kernel(const float* __restrict__ net, const float* __restrict__ x_in,
                   const float* __restrict__ logd, float* __restrict__ phi_out,
                   float* __restrict__ log_out) {
    const int b = blockIdx.x;
    const int tid = threadIdx.x;
    const float* row = net + (size_t)b * OUTW;

    __shared__ float sh[256 * NC];
    __shared__ float red[256];

    float lsum = 0.f;

    for (int chunk = 0; chunk < 8; chunk++) {
        __syncthreads();
        for (int i = tid; i < 256 * NC; i += 256)
            sh[i] = row[chunk * 256 * NC + i];
        __syncthreads();

        const int s = chunk * 256 + tid;
        const float* p = sh + tid * NC;

        float hr[9], wr[8];
#pragma unroll
        for (int c = 0; c < 9; c++) hr[c] = p[c];
#pragma unroll
        for (int c = 0; c < 8; c++) wr[c] = p[9 + c];

        float m = wr[0];
#pragma unroll
        for (int c = 1; c < 8; c++) m = fmaxf(m, wr[c]);
        float wn[8];
        float wsum = 0.f;
#pragma unroll
        for (int c = 0; c < 8; c++) { wn[c] = expf(wr[c] - m); wsum += wn[c]; }
        float winv = 1.0f / wsum;
#pragma unroll
        for (int c = 0; c < 8; c++) wn[c] *= winv;

        float eh[9];
#pragma unroll
        for (int c = 0; c < 9; c++) eh[c] = expf(hr[c]);
        float denom = 0.f;
#pragma unroll
        for (int c = 0; c < 8; c++) denom += 0.5f * wn[c] * (eh[c] + eh[c + 1]);
        float dinv = 1.0f / denom;
        float hn[9];
#pragma unroll
        for (int c = 0; c < 9; c++) hn[c] = eh[c] * dinv;

        const float x = x_in[(size_t)b * SIZE_D + s] * 0.31830988618379067154f;

        float cum = 0.f, phicum = 0.f;
        float wk = wn[0], hk = hn[0], hk1 = hn[1];
        float xkm1 = -EPS_C, phikm1 = 0.f;
#pragma unroll
        for (int i = 0; i < 7; i++) {
            float trap = 0.5f * wn[i] * (hn[i] + hn[i + 1]);
            cum += wn[i];
            phicum += trap;
            bool c = (cum < x);
            wk     = c ? wn[i + 1] : wk;
            hk     = c ? hn[i + 1] : hk;
            hk1    = c ? hn[i + 2] : hk1;
            xkm1   = c ? cum      : xkm1;
            phikm1 = c ? phicum   : phikm1;
        }

        float alpha = (x - xkm1) / wk;
        float phi = phikm1 + alpha * hk * wk
                  + 0.5f * alpha * alpha * (hk1 - hk) * wk;
        phi_out[(size_t)b * SIZE_D + s] = phi;
        lsum += logf(hk + alpha * (hk1 - hk));
    }

    red[tid] = lsum;
    __syncthreads();
    for (int o = 128; o > 0; o >>= 1) {
        if (tid < o) red[tid] += red[tid + o];
        __syncthreads();
    }
    if (tid == 0) log_out[b] = logd[b] - red[0];
}

// ---------------- launch ----------------
extern "C" void kernel_launch(void* const* d_in, const int* in_sizes, int n_in,
                              void* d_out, int out_size) {
    (void)in_sizes; (void)n_in; (void)out_size;
    const float* x_in      = (const float*)d_in[0];
    const float* x_passive = (const float*)d_in[1];
    const float* log_dens  = (const float*)d_in[2];
    const float* w1        = (const float*)d_in[3];
    const float* b1        = (const float*)d_in[4];
    const float* w2        = (const float*)d_in[5];
    const float* b2        = (const float*)d_in[6];

    float* out_phi = (float*)d_out;
    float* out_log = (float*)d_out + (size_t)NTOT;

    __half *xh, *w1t, *hbuf, *w2t;
    float *nbuf, *csum;
    cudaGetSymbolAddress((void**)&xh, g_xh);
    cudaGetSymbolAddress((void**)&w1t, g_w1t);
    cudaGetSymbolAddress((void**)&hbuf, g_h);
    cudaGetSymbolAddress((void**)&w2t, g_w2t);
    cudaGetSymbolAddress((void**)&nbuf, g_net);
    cudaGetSymbolAddress((void**)&csum, g_colsum);

    cudaFuncSetAttribute(gemm_fp16<0>, cudaFuncAttributeMaxDynamicSharedMemorySize,
                         GEMM_SMEM);
    cudaFuncSetAttribute(gemm_fp16<1>, cudaFuncAttributeMaxDynamicSharedMemorySize,
                         GEMM_SMEM);

    // 0) stats partials + x fp16 convert + colsum zero (fused)
    stat_split<<<NSTATBLK, 256>>>(x_passive, xh);
    // 1) stats finalize
    stat_pass2<<<1, 1024>>>(NSTATBLK, NTOT);
    // 2) w1 transpose + colsum accumulate
    transpose_half<1><<<dim3(HID / 32, SIZE_D / 32), 256>>>(w1, w1t, SIZE_D, HID);
    // 3) w2 transpose
    transpose_half<0><<<dim3(OUTW / 32, HID / 32), 256>>>(w2, w2t, HID, OUTW);
    // 4) GEMM1: h = tanh(xs @ w1 + b1) -> fp16
    gemm_fp16<0><<<dim3(BATCH / GBM, HID / GBN), 256, GEMM_SMEM>>>(
        xh, w1t, b1, csum, nullptr, hbuf, SIZE_D, HID, SIZE_D / GBK);
    // 5) GEMM2: net = tanh(h @ w2 + b2) -> fp32
    gemm_fp16<1><<<dim3(BATCH / GBM, OUTW / GBN), 256, GEMM_SMEM>>>(
        hbuf, w2t, b2, nullptr, nbuf, nullptr, HID, OUTW, HID / GBK);
    // 6) spline + per-row log-density reduction
    spline_kernel<<<BATCH, 256>>>(nbuf, x_in, log_dens, out_phi, out_log);
}

// round 9
// speedup vs baseline: 6.2251x; 1.0160x over previous
#include <cuda_runtime.h>
#include <cuda_fp16.h>
#include <math.h>
#include <stdint.h>

// ---------------- problem constants ----------------
#define BATCH 2048
#define SIZE_D 2048
#define HID 1024
#define NC 17
#define OUTW (SIZE_D * NC)   // 34816
#define NTOT (BATCH * SIZE_D)
#define EPS_C 1e-6f
#define NSTATBLK (NTOT / 4 / 256)   // 4096

// ---------------- GEMM tiling ----------------
#define GBM 128
#define GBN 128
#define GBK 32
#define GSTAGES 5
#define TILE_B (GBM * 64)        // 128 rows x 32 fp16 (64B/row) = 8192B
#define STAGE_B (2 * TILE_B)     // A, B = 16384B
#define GEMM_SMEM (GSTAGES * STAGE_B)  // 81920 -> 2 CTAs/SM

// ---------------- device scratch (allocation-free rule) ----------------
__device__ __half g_xh[(size_t)NTOT];                 // x_passive fp16
__device__ __half g_w1t[(size_t)HID * SIZE_D];        // [1024][2048] fp16
__device__ __half g_h[(size_t)BATCH * HID];           // h fp16 (A of GEMM2)
__device__ __half g_w2t[(size_t)OUTW * HID];          // [34816][1024] fp16
__device__ __half g_net[(size_t)BATCH * OUTW];        // net fp16 (143 MB)
__device__ float g_colsum[HID];
__device__ float g_part_s[NSTATBLK];
__device__ float g_part_ss[NSTATBLK];
__device__ float g_stats[2];

// ---------------- PTX helpers ----------------
__device__ __forceinline__ uint32_t smem_u32(const void* p) {
    uint32_t a;
    asm("{ .reg .u64 t; cvta.to.shared.u64 t, %1; cvt.u32.u64 %0, t; }"
        : "=r"(a) : "l"(p));
    return a;
}
__device__ __forceinline__ void cp_async16(uint32_t sa, const void* ga) {
    asm volatile("cp.async.cg.shared.global [%0], [%1], 16;"
                 :: "r"(sa), "l"(ga) : "memory");
}
__device__ __forceinline__ void cp_commit() {
    asm volatile("cp.async.commit_group;" ::: "memory");
}
template <int N>
__device__ __forceinline__ void cp_wait() {
    asm volatile("cp.async.wait_group %0;" :: "n"(N) : "memory");
}
__device__ __forceinline__ void ldmatrix_x4(uint32_t* r, uint32_t addr) {
    asm volatile("ldmatrix.sync.aligned.m8n8.x4.shared.b16 {%0,%1,%2,%3}, [%4];"
                 : "=r"(r[0]), "=r"(r[1]), "=r"(r[2]), "=r"(r[3])
                 : "r"(addr));
}
__device__ __forceinline__ void mma16816(float* c, const uint32_t* a,
                                         uint32_t b0, uint32_t b1) {
    asm volatile(
        "mma.sync.aligned.m16n8k16.row.col.f32.f16.f16.f32 "
        "{%0,%1,%2,%3}, {%4,%5,%6,%7}, {%8,%9}, {%0,%1,%2,%3};"
        : "+f"(c[0]), "+f"(c[1]), "+f"(c[2]), "+f"(c[3])
        : "r"(a[0]), "r"(a[1]), "r"(a[2]), "r"(a[3]), "r"(b0), "r"(b1));
}
__device__ __forceinline__ uint32_t sw_off(int row, int ch) {
    return ((uint32_t)row << 6) + (((ch ^ (row >> 1)) & 3) << 4);
}

// ---------------- stats pass 1 (fused with x fp16 convert) ----------------
__global__ __launch_bounds__(256)
void stat_split(const float* __restrict__ xp, __half* __restrict__ xh) {
    const int i = blockIdx.x * blockDim.x + threadIdx.x;
    float4 v = ((const float4*)xp)[i];

    __half2 p0 = {__float2half_rn(v.x), __float2half_rn(v.y)};
    __half2 p1 = {__float2half_rn(v.z), __float2half_rn(v.w)};
    uint2 hv = {*(uint32_t*)&p0, *(uint32_t*)&p1};
    ((uint2*)xh)[i] = hv;

    if (blockIdx.x == 0) {
#pragma unroll
        for (int c = 0; c < HID / 256; c++)
            g_colsum[threadIdx.x + c * 256] = 0.f;
    }

    float s = v.x + v.y + v.z + v.w;
    float ss = v.x * v.x + v.y * v.y + v.z * v.z + v.w * v.w;
    __shared__ float shs[256];
    __shared__ float shss[256];
    int tid = threadIdx.x;
    shs[tid] = s; shss[tid] = ss;
    __syncthreads();
    for (int o = 128; o > 0; o >>= 1) {
        if (tid < o) { shs[tid] += shs[tid + o]; shss[tid] += shss[tid + o]; }
        __syncthreads();
    }
    if (tid == 0) { g_part_s[blockIdx.x] = shs[0]; g_part_ss[blockIdx.x] = shss[0]; }
}

__global__ void stat_pass2(int nblocks, int n) {
    __shared__ float shs[1024];
    __shared__ float shss[1024];
    int tid = threadIdx.x;
    float s = 0.f, ss = 0.f;
    for (int i = tid; i < nblocks; i += 1024) { s += g_part_s[i]; ss += g_part_ss[i]; }
    shs[tid] = s; shss[tid] = ss;
    __syncthreads();
    for (int o = 512; o > 0; o >>= 1) {
        if (tid < o) { shs[tid] += shs[tid + o]; shss[tid] += shss[tid + o]; }
        __syncthreads();
    }
    if (tid == 0) {
        float S = shs[0], SS = shss[0];
        float mean = S / (float)n;
        float var = (SS - S * mean) / (float)(n - 1);
        g_stats[0] = mean;
        g_stats[1] = rsqrtf(var);
    }
}

// ---------------- transpose -> fp16 (optional column sums) ----------------
template <int DOCOLSUM>
__global__ __launch_bounds__(256)
void transpose_half(const float* __restrict__ src,
                    __half* __restrict__ dst, int K, int N) {
    __shared__ float t[32][33];
    const int n0 = blockIdx.x * 32;
    const int k0 = blockIdx.y * 32;
    const int tx = threadIdx.x & 31;
    const int ty = threadIdx.x >> 5;
#pragma unroll
    for (int i = 0; i < 32; i += 8)
        t[ty + i][tx] = src[(size_t)(k0 + ty + i) * N + n0 + tx];
    __syncthreads();
    if (DOCOLSUM && threadIdx.x < 32) {
        float s = 0.f;
#pragma unroll
        for (int r = 0; r < 32; r++) s += t[r][threadIdx.x];
        atomicAdd(&g_colsum[n0 + threadIdx.x], s);
    }
#pragma unroll
    for (int i = 0; i < 32; i += 8) {
        dst[(size_t)(n0 + ty + i) * K + k0 + tx] = __float2half_rn(t[tx][ty + i]);
    }
}

// ---------------- plain fp16 GEMM (fp32 accumulate, fp16 out) ----------------
// C = tanh(scale * (A @ B^T) + bias_eff), fp16 output.
//   EPI==0: scale=invstd, bias_eff=b1-mean*invstd*colsum
//   EPI==1: scale=1, bias_eff=bias
// Single-barrier pipeline: after the post-wait barrier all warps have finished
// iteration kt-1, so overwriting stage (kt-1 mod G) is safe immediately.
template <int EPI>
__global__ __launch_bounds__(256, 2)
void gemm_fp16(const __half* __restrict__ A,
               const __half* __restrict__ B,
               const float* __restrict__ bias,
               const float* __restrict__ colsum,
               __half* __restrict__ C,
               int K, int Nout, int KTILES) {
    extern __shared__ __align__(128) char smem[];
    const uint32_t sb = smem_u32(smem);
    const int tid = threadIdx.x;
    const int wid = tid >> 5;
    const int lane = tid & 31;
    const int wm = wid & 3;
    const int wn = wid >> 2;
    const int m0 = blockIdx.x * GBM;
    const int n0 = blockIdx.y * GBN;

    const int r0c = tid >> 2, c0c = tid & 3;
    const int r1c = (tid + 256) >> 2;

    float acc[2][8][4];
#pragma unroll
    for (int a = 0; a < 2; a++)
#pragma unroll
        for (int b = 0; b < 8; b++)
#pragma unroll
            for (int c = 0; c < 4; c++) acc[a][b][c] = 0.f;

    auto load_stage = [&](int s, int kt) {
        const uint32_t base = sb + s * STAGE_B;
        const size_t kof = (size_t)kt * GBK;
        {
            uint32_t so = sw_off(r0c, c0c);
            size_t ga = (size_t)(m0 + r0c) * K + kof + c0c * 8;
            size_t gb = (size_t)(n0 + r0c) * K + kof + c0c * 8;
            cp_async16(base + 0 * TILE_B + so, A + ga);
            cp_async16(base + 1 * TILE_B + so, B + gb);
        }
        {
            uint32_t so = sw_off(r1c, c0c);
            size_t ga = (size_t)(m0 + r1c) * K + kof + c0c * 8;
            size_t gb = (size_t)(n0 + r1c) * K + kof + c0c * 8;
            cp_async16(base + 0 * TILE_B + so, A + ga);
            cp_async16(base + 1 * TILE_B + so, B + gb);
        }
    };

#pragma unroll
    for (int s = 0; s < GSTAGES - 1; s++) {
        load_stage(s, s);
        cp_commit();
    }

    const int lrow = lane & 15;
    const int lhalf = lane >> 4;

    int cs = 0;
    int ls = GSTAGES - 1;
    for (int kt = 0; kt < KTILES; kt++) {
        cp_wait<GSTAGES - 2>();
        __syncthreads();

        // issue next load FIRST (stage ls aliases kt-1, finished by all warps)
        const int nk = kt + GSTAGES - 1;
        if (nk < KTILES) load_stage(ls, nk);
        cp_commit();

        const uint32_t sA = sb + cs * STAGE_B;
        const uint32_t sB = sA + TILE_B;

#pragma unroll
        for (int k16 = 0; k16 < 2; k16++) {
            const int kc = k16 * 2 + lhalf;
            uint32_t afr[2][4];
#pragma unroll
            for (int mt = 0; mt < 2; mt++) {
                int row = wm * 32 + mt * 16 + lrow;
                ldmatrix_x4(afr[mt], sA + sw_off(row, kc));
            }
#pragma unroll
            for (int g = 0; g < 4; g++) {
                int row = wn * 64 + g * 16 + lrow;
                uint32_t bfr[4];
                ldmatrix_x4(bfr, sB + sw_off(row, kc));
#pragma unroll
                for (int mt = 0; mt < 2; mt++) {
#pragma unroll
                    for (int p = 0; p < 2; p++) {
                        mma16816(acc[mt][g * 2 + p], afr[mt], bfr[p], bfr[2 + p]);
                    }
                }
            }
        }
        cs = (cs + 1 == GSTAGES) ? 0 : cs + 1;
        ls = (ls + 1 == GSTAGES) ? 0 : ls + 1;
    }

    // ---------------- epilogue ----------------
    float mean = 0.f, invstd = 1.f;
    if (EPI == 0) { mean = g_stats[0]; invstd = g_stats[1]; }

    const int r_base = m0 + wm * 32 + (lane >> 2);
    const int c_base = n0 + wn * 64 + (lane & 3) * 2;

#pragma unroll
    for (int mt = 0; mt < 2; mt++) {
#pragma unroll
        for (int nf = 0; nf < 8; nf++) {
            const int col = c_base + nf * 8;
            float be0, be1;
            if (EPI == 0) {
                be0 = bias[col]     - mean * invstd * colsum[col];
                be1 = bias[col + 1] - mean * invstd * colsum[col + 1];
            } else {
                be0 = bias[col];
                be1 = bias[col + 1];
            }
#pragma unroll
            for (int hh = 0; hh < 2; hh++) {
                const int row = r_base + mt * 16 + hh * 8;
                float v0 = acc[mt][nf][hh * 2 + 0];
                float v1 = acc[mt][nf][hh * 2 + 1];
                if (EPI == 0) {
                    v0 = tanhf(fmaf(invstd, v0, be0));
                    v1 = tanhf(fmaf(invstd, v1, be1));
                } else {
                    v0 = tanhf(v0 + be0);
                    v1 = tanhf(v1 + be1);
                }
                __half2 hp = {__float2half_rn(v0), __float2half_rn(v1)};
                *(__half2*)(C + (size_t)row * Nout + col) = hp;
            }
        }
    }
}

// ---------------- spline evaluation + per-row log reduction ----------------
__global__ __launch_bounds__(256)
void spline_kernel(const __half* __restrict__ net, const float* __restrict__ x_in,
                   const float* __restrict__ logd, float* __restrict__ phi_out,
                   float* __restrict__ log_out) {
    const int b = blockIdx.x;
    const int tid = threadIdx.x;
    const __half* row = net + (size_t)b * OUTW;

    __shared__ float sh[256 * NC];
    __shared__ float red[256];

    float lsum = 0.f;

    for (int chunk = 0; chunk < 8; chunk++) {
        __syncthreads();
        // 256*17 halfs = 2176 half2 pairs; chunk base is even -> 4B aligned
        const __half2* rowc = (const __half2*)(row + (size_t)chunk * 256 * NC);
        for (int i = tid; i < 128 * NC; i += 256) {
            float2 v = __half22float2(rowc[i]);
            sh[2 * i]     = v.x;
            sh[2 * i + 1] = v.y;
        }
        __syncthreads();

        const int s = chunk * 256 + tid;
        const float* p = sh + tid * NC;

        float hr[9], wr[8];
#pragma unroll
        for (int c = 0; c < 9; c++) hr[c] = p[c];
#pragma unroll
        for (int c = 0; c < 8; c++) wr[c] = p[9 + c];

        float m = wr[0];
#pragma unroll
        for (int c = 1; c < 8; c++) m = fmaxf(m, wr[c]);
        float wn[8];
        float wsum = 0.f;
#pragma unroll
        for (int c = 0; c < 8; c++) { wn[c] = expf(wr[c] - m); wsum += wn[c]; }
        float winv = 1.0f / wsum;
#pragma unroll
        for (int c = 0; c < 8; c++) wn[c] *= winv;

        float eh[9];
#pragma unroll
        for (int c = 0; c < 9; c++) eh[c] = expf(hr[c]);
        float denom = 0.f;
#pragma unroll
        for (int c = 0; c < 8; c++) denom += 0.5f * wn[c] * (eh[c] + eh[c + 1]);
        float dinv = 1.0f / denom;
        float hn[9];
#pragma unroll
        for (int c = 0; c < 9; c++) hn[c] = eh[c] * dinv;

        const float x = x_in[(size_t)b * SIZE_D + s] * 0.31830988618379067154f;

        float cum = 0.f, phicum = 0.f;
        float wk = wn[0], hk = hn[0], hk1 = hn[1];
        float xkm1 = -EPS_C, phikm1 = 0.f;
#pragma unroll
        for (int i = 0; i < 7; i++) {
            float trap = 0.5f * wn[i] * (hn[i] + hn[i + 1]);
            cum += wn[i];
            phicum += trap;
            bool c = (cum < x);
            wk     = c ? wn[i + 1] : wk;
            hk     = c ? hn[i + 1] : hk;
            hk1    = c ? hn[i + 2] : hk1;
            xkm1   = c ? cum      : xkm1;
            phikm1 = c ? phicum   : phikm1;
        }

        float alpha = (x - xkm1) / wk;
        float phi = phikm1 + alpha * hk * wk
                  + 0.5f * alpha * alpha * (hk1 - hk) * wk;
        phi_out[(size_t)b * SIZE_D + s] = phi;
        lsum += logf(hk + alpha * (hk1 - hk));
    }

    red[tid] = lsum;
    __syncthreads();
    for (int o = 128; o > 0; o >>= 1) {
        if (tid < o) red[tid] += red[tid + o];
        __syncthreads();
    }
    if (tid == 0) log_out[b] = logd[b] - red[0];
}

// ---------------- launch ----------------
extern "C" void kernel_launch(void* const* d_in, const int* in_sizes, int n_in,
                              void* d_out, int out_size) {
    (void)in_sizes; (void)n_in; (void)out_size;
    const float* x_in      = (const float*)d_in[0];
    const float* x_passive = (const float*)d_in[1];
    const float* log_dens  = (const float*)d_in[2];
    const float* w1        = (const float*)d_in[3];
    const float* b1        = (const float*)d_in[4];
    const float* w2        = (const float*)d_in[5];
    const float* b2        = (const float*)d_in[6];

    float* out_phi = (float*)d_out;
    float* out_log = (float*)d_out + (size_t)NTOT;

    __half *xh, *w1t, *hbuf, *w2t, *nbuf;
    float *csum;
    cudaGetSymbolAddress((void**)&xh, g_xh);
    cudaGetSymbolAddress((void**)&w1t, g_w1t);
    cudaGetSymbolAddress((void**)&hbuf, g_h);
    cudaGetSymbolAddress((void**)&w2t, g_w2t);
    cudaGetSymbolAddress((void**)&nbuf, g_net);
    cudaGetSymbolAddress((void**)&csum, g_colsum);

    cudaFuncSetAttribute(gemm_fp16<0>, cudaFuncAttributeMaxDynamicSharedMemorySize,
                         GEMM_SMEM);
    cudaFuncSetAttribute(gemm_fp16<1>, cudaFuncAttributeMaxDynamicSharedMemorySize,
                         GEMM_SMEM);

    // 0) stats partials + x fp16 convert + colsum zero (fused)
    stat_split<<<NSTATBLK, 256>>>(x_passive, xh);
    // 1) stats finalize
    stat_pass2<<<1, 1024>>>(NSTATBLK, NTOT);
    // 2) w1 transpose + colsum accumulate
    transpose_half<1><<<dim3(HID / 32, SIZE_D / 32), 256>>>(w1, w1t, SIZE_D, HID);
    // 3) w2 transpose
    transpose_half<0><<<dim3(OUTW / 32, HID / 32), 256>>>(w2, w2t, HID, OUTW);
    // 4) GEMM1: h = tanh(xs @ w1 + b1) -> fp16
    gemm_fp16<0><<<dim3(BATCH / GBM, HID / GBN), 256, GEMM_SMEM>>>(
        xh, w1t, b1, csum, hbuf, SIZE_D, HID, SIZE_D / GBK);
    // 5) GEMM2: net = tanh(h @ w2 + b2) -> fp16
    gemm_fp16<1><<<dim3(BATCH / GBM, OUTW / GBN), 256, GEMM_SMEM>>>(
        hbuf, w2t, b2, nullptr, nbuf, HID, OUTW, HID / GBK);
    // 6) spline + per-row log-density reduction
    spline_kernel<<<BATCH, 256>>>(nbuf, x_in, log_dens, out_phi, out_log);
}

// round 10
// speedup vs baseline: 6.3162x; 1.0146x over previous
#include <cuda_runtime.h>
#include <cuda_fp16.h>
#include <math.h>
#include <stdint.h>

// ---------------- problem constants ----------------
#define BATCH 2048
#define SIZE_D 2048
#define HID 1024
#define NC 17
#define OUTW (SIZE_D * NC)   // 34816
#define NTOT (BATCH * SIZE_D)
#define EPS_C 1e-6f
#define NSTATBLK (NTOT / 4 / 256)   // 4096

// ---------------- GEMM tiling ----------------
#define GBM 128
#define GBN 128
#define GBK 32
#define GSTAGES 5
#define TILE_B (GBM * 64)
#define STAGE_B (2 * TILE_B)
#define GEMM_SMEM (GSTAGES * STAGE_B)  // 81920 -> 2 CTAs/SM

// ---------------- device scratch ----------------
__device__ __half g_xh[(size_t)NTOT];
__device__ __half g_w1t[(size_t)HID * SIZE_D];
__device__ __half g_h[(size_t)BATCH * HID];
__device__ __half g_w2t[(size_t)OUTW * HID];
__device__ __half g_net[(size_t)BATCH * OUTW];
__device__ float g_colsum[HID];
__device__ float g_part_s[NSTATBLK];
__device__ float g_part_ss[NSTATBLK];
__device__ float g_stats[2];

// ---------------- PTX helpers ----------------
__device__ __forceinline__ uint32_t smem_u32(const void* p) {
    uint32_t a;
    asm("{ .reg .u64 t; cvta.to.shared.u64 t, %1; cvt.u32.u64 %0, t; }"
        : "=r"(a) : "l"(p));
    return a;
}
__device__ __forceinline__ void cp_async16(uint32_t sa, const void* ga) {
    asm volatile("cp.async.cg.shared.global [%0], [%1], 16;"
                 :: "r"(sa), "l"(ga) : "memory");
}
__device__ __forceinline__ void cp_commit() {
    asm volatile("cp.async.commit_group;" ::: "memory");
}
template <int N>
__device__ __forceinline__ void cp_wait() {
    asm volatile("cp.async.wait_group %0;" :: "n"(N) : "memory");
}
__device__ __forceinline__ void ldmatrix_x4(uint32_t* r, uint32_t addr) {
    asm volatile("ldmatrix.sync.aligned.m8n8.x4.shared.b16 {%0,%1,%2,%3}, [%4];"
                 : "=r"(r[0]), "=r"(r[1]), "=r"(r[2]), "=r"(r[3])
                 : "r"(addr));
}
__device__ __forceinline__ void mma16816(float* c, const uint32_t* a,
                                         uint32_t b0, uint32_t b1) {
    asm volatile(
        "mma.sync.aligned.m16n8k16.row.col.f32.f16.f16.f32 "
        "{%0,%1,%2,%3}, {%4,%5,%6,%7}, {%8,%9}, {%0,%1,%2,%3};"
        : "+f"(c[0]), "+f"(c[1]), "+f"(c[2]), "+f"(c[3])
        : "r"(a[0]), "r"(a[1]), "r"(a[2]), "r"(a[3]), "r"(b0), "r"(b1));
}
__device__ __forceinline__ uint32_t sw_off(int row, int ch) {
    return ((uint32_t)row << 6) + (((ch ^ (row >> 1)) & 3) << 4);
}

// exact identity tanh via hardware exp: 1 - 2/(e^{2x}+1)
__device__ __forceinline__ float fast_tanh(float x) {
    float e = __expf(2.0f * x);
    return 1.0f - 2.0f / (e + 1.0f);
}

// ---------------- stats pass 1 (fused with x fp16 convert) ----------------
__global__ __launch_bounds__(256)
void stat_split(const float* __restrict__ xp, __half* __restrict__ xh) {
    const int i = blockIdx.x * blockDim.x + threadIdx.x;
    float4 v = ((const float4*)xp)[i];

    __half2 p0 = {__float2half_rn(v.x), __float2half_rn(v.y)};
    __half2 p1 = {__float2half_rn(v.z), __float2half_rn(v.w)};
    uint2 hv = {*(uint32_t*)&p0, *(uint32_t*)&p1};
    ((uint2*)xh)[i] = hv;

    if (blockIdx.x == 0) {
#pragma unroll
        for (int c = 0; c < HID / 256; c++)
            g_colsum[threadIdx.x + c * 256] = 0.f;
    }

    float s = v.x + v.y + v.z + v.w;
    float ss = v.x * v.x + v.y * v.y + v.z * v.z + v.w * v.w;
    __shared__ float shs[256];
    __shared__ float shss[256];
    int tid = threadIdx.x;
    shs[tid] = s; shss[tid] = ss;
    __syncthreads();
    for (int o = 128; o > 0; o >>= 1) {
        if (tid < o) { shs[tid] += shs[tid + o]; shss[tid] += shss[tid + o]; }
        __syncthreads();
    }
    if (tid == 0) { g_part_s[blockIdx.x] = shs[0]; g_part_ss[blockIdx.x] = shss[0]; }
}

__global__ void stat_pass2(int nblocks, int n) {
    __shared__ float shs[1024];
    __shared__ float shss[1024];
    int tid = threadIdx.x;
    float s = 0.f, ss = 0.f;
    for (int i = tid; i < nblocks; i += 1024) { s += g_part_s[i]; ss += g_part_ss[i]; }
    shs[tid] = s; shss[tid] = ss;
    __syncthreads();
    for (int o = 512; o > 0; o >>= 1) {
        if (tid < o) { shs[tid] += shs[tid + o]; shss[tid] += shss[tid + o]; }
        __syncthreads();
    }
    if (tid == 0) {
        float S = shs[0], SS = shss[0];
        float mean = S / (float)n;
        float var = (SS - S * mean) / (float)(n - 1);
        g_stats[0] = mean;
        g_stats[1] = rsqrtf(var);
    }
}

// ---------------- transpose -> fp16, 64x64 tiles, vectorized ----------------
// src [K][N] fp32 -> dst [N][K] fp16
template <int DOCOLSUM>
__global__ __launch_bounds__(256)
void transpose_half(const float* __restrict__ src,
                    __half* __restrict__ dst, int K, int N) {
    __shared__ float t[64][65];
    const int n0 = blockIdx.x * 64;
    const int k0 = blockIdx.y * 64;
    const int tid = threadIdx.x;

    const int lr = tid >> 4;          // 0..15
    const int lc = (tid & 15) * 4;    // 0..60
#pragma unroll
    for (int i = 0; i < 64; i += 16) {
        float4 v = *(const float4*)(src + (size_t)(k0 + lr + i) * N + n0 + lc);
        t[lr + i][lc + 0] = v.x;
        t[lr + i][lc + 1] = v.y;
        t[lr + i][lc + 2] = v.z;
        t[lr + i][lc + 3] = v.w;
    }
    __syncthreads();

    if (DOCOLSUM && tid < 64) {
        float s = 0.f;
#pragma unroll
        for (int r = 0; r < 64; r++) s += t[r][tid];
        atomicAdd(&g_colsum[n0 + tid], s);
    }

    const int wid = tid >> 5;
    const int lane = tid & 31;
#pragma unroll
    for (int i = 0; i < 64; i += 8) {
        const int r = wid + i;        // dst row n0+r
        const int k = lane * 2;
        __half2 hp = {__float2half_rn(t[k][r]), __float2half_rn(t[k + 1][r])};
        *(__half2*)(dst + (size_t)(n0 + r) * K + k0 + k) = hp;
    }
}

// ---------------- plain fp16 GEMM (fp32 accumulate, fp16 out) ----------------
template <int EPI>
__global__ __launch_bounds__(256, 2)
void gemm_fp16(const __half* __restrict__ A,
               const __half* __restrict__ B,
               const float* __restrict__ bias,
               const float* __restrict__ colsum,
               __half* __restrict__ C,
               int K, int Nout, int KTILES) {
    extern __shared__ __align__(128) char smem[];
    const uint32_t sb = smem_u32(smem);
    const int tid = threadIdx.x;
    const int wid = tid >> 5;
    const int lane = tid & 31;
    const int wm = wid & 3;
    const int wn = wid >> 2;
    const int m0 = blockIdx.x * GBM;
    const int n0 = blockIdx.y * GBN;

    const int r0c = tid >> 2, c0c = tid & 3;
    const int r1c = (tid + 256) >> 2;

    float acc[2][8][4];
#pragma unroll
    for (int a = 0; a < 2; a++)
#pragma unroll
        for (int b = 0; b < 8; b++)
#pragma unroll
            for (int c = 0; c < 4; c++) acc[a][b][c] = 0.f;

    auto load_stage = [&](int s, int kt) {
        const uint32_t base = sb + s * STAGE_B;
        const size_t kof = (size_t)kt * GBK;
        {
            uint32_t so = sw_off(r0c, c0c);
            size_t ga = (size_t)(m0 + r0c) * K + kof + c0c * 8;
            size_t gb = (size_t)(n0 + r0c) * K + kof + c0c * 8;
            cp_async16(base + 0 * TILE_B + so, A + ga);
            cp_async16(base + 1 * TILE_B + so, B + gb);
        }
        {
            uint32_t so = sw_off(r1c, c0c);
            size_t ga = (size_t)(m0 + r1c) * K + kof + c0c * 8;
            size_t gb = (size_t)(n0 + r1c) * K + kof + c0c * 8;
            cp_async16(base + 0 * TILE_B + so, A + ga);
            cp_async16(base + 1 * TILE_B + so, B + gb);
        }
    };

#pragma unroll
    for (int s = 0; s < GSTAGES - 1; s++) {
        load_stage(s, s);
        cp_commit();
    }

    const int lrow = lane & 15;
    const int lhalf = lane >> 4;

    int cs = 0;
    int ls = GSTAGES - 1;
    for (int kt = 0; kt < KTILES; kt++) {
        cp_wait<GSTAGES - 2>();
        __syncthreads();

        const int nk = kt + GSTAGES - 1;
        if (nk < KTILES) load_stage(ls, nk);
        cp_commit();

        const uint32_t sA = sb + cs * STAGE_B;
        const uint32_t sB = sA + TILE_B;

#pragma unroll
        for (int k16 = 0; k16 < 2; k16++) {
            const int kc = k16 * 2 + lhalf;
            uint32_t afr[2][4];
#pragma unroll
            for (int mt = 0; mt < 2; mt++) {
                int row = wm * 32 + mt * 16 + lrow;
                ldmatrix_x4(afr[mt], sA + sw_off(row, kc));
            }
#pragma unroll
            for (int g = 0; g < 4; g++) {
                int row = wn * 64 + g * 16 + lrow;
                uint32_t bfr[4];
                ldmatrix_x4(bfr, sB + sw_off(row, kc));
#pragma unroll
                for (int mt = 0; mt < 2; mt++) {
#pragma unroll
                    for (int p = 0; p < 2; p++) {
                        mma16816(acc[mt][g * 2 + p], afr[mt], bfr[p], bfr[2 + p]);
                    }
                }
            }
        }
        cs = (cs + 1 == GSTAGES) ? 0 : cs + 1;
        ls = (ls + 1 == GSTAGES) ? 0 : ls + 1;
    }

    // ---------------- epilogue ----------------
    float mean = 0.f, invstd = 1.f;
    if (EPI == 0) { mean = g_stats[0]; invstd = g_stats[1]; }

    const int r_base = m0 + wm * 32 + (lane >> 2);
    const int c_base = n0 + wn * 64 + (lane & 3) * 2;

#pragma unroll
    for (int mt = 0; mt < 2; mt++) {
#pragma unroll
        for (int nf = 0; nf < 8; nf++) {
            const int col = c_base + nf * 8;
            float be0, be1;
            if (EPI == 0) {
                be0 = bias[col]     - mean * invstd * colsum[col];
                be1 = bias[col + 1] - mean * invstd * colsum[col + 1];
            } else {
                be0 = bias[col];
                be1 = bias[col + 1];
            }
#pragma unroll
            for (int hh = 0; hh < 2; hh++) {
                const int row = r_base + mt * 16 + hh * 8;
                float v0 = acc[mt][nf][hh * 2 + 0];
                float v1 = acc[mt][nf][hh * 2 + 1];
                if (EPI == 0) {
                    v0 = fast_tanh(fmaf(invstd, v0, be0));
                    v1 = fast_tanh(fmaf(invstd, v1, be1));
                } else {
                    v0 = fast_tanh(v0 + be0);
                    v1 = fast_tanh(v1 + be1);
                }
                __half2 hp = {__float2half_rn(v0), __float2half_rn(v1)};
                *(__half2*)(C + (size_t)row * Nout + col) = hp;
            }
        }
    }
}

// ---------------- spline evaluation + per-row log reduction ----------------
__global__ __launch_bounds__(256)
void spline_kernel(const __half* __restrict__ net, const float* __restrict__ x_in,
                   const float* __restrict__ logd, float* __restrict__ phi_out,
                   float* __restrict__ log_out) {
    const int b = blockIdx.x;
    const int tid = threadIdx.x;
    const __half* row = net + (size_t)b * OUTW;

    __shared__ float sh[256 * NC];
    __shared__ float red[256];

    float lsum = 0.f;

    for (int chunk = 0; chunk < 8; chunk++) {
        __syncthreads();
        const __half2* rowc = (const __half2*)(row + (size_t)chunk * 256 * NC);
        for (int i = tid; i < 128 * NC; i += 256) {
            float2 v = __half22float2(rowc[i]);
            sh[2 * i]     = v.x;
            sh[2 * i + 1] = v.y;
        }
        __syncthreads();

        const int s = chunk * 256 + tid;
        const float* p = sh + tid * NC;

        float hr[9], wr[8];
#pragma unroll
        for (int c = 0; c < 9; c++) hr[c] = p[c];
#pragma unroll
        for (int c = 0; c < 8; c++) wr[c] = p[9 + c];

        float m = wr[0];
#pragma unroll
        for (int c = 1; c < 8; c++) m = fmaxf(m, wr[c]);
        float wn[8];
        float wsum = 0.f;
#pragma unroll
        for (int c = 0; c < 8; c++) { wn[c] = __expf(wr[c] - m); wsum += wn[c]; }
        float winv = 1.0f / wsum;
#pragma unroll
        for (int c = 0; c < 8; c++) wn[c] *= winv;

        float eh[9];
#pragma unroll
        for (int c = 0; c < 9; c++) eh[c] = __expf(hr[c]);
        float denom = 0.f;
#pragma unroll
        for (int c = 0; c < 8; c++) denom += 0.5f * wn[c] * (eh[c] + eh[c + 1]);
        float dinv = 1.0f / denom;
        float hn[9];
#pragma unroll
        for (int c = 0; c < 9; c++) hn[c] = eh[c] * dinv;

        const float x = x_in[(size_t)b * SIZE_D + s] * 0.31830988618379067154f;

        float cum = 0.f, phicum = 0.f;
        float wk = wn[0], hk = hn[0], hk1 = hn[1];
        float xkm1 = -EPS_C, phikm1 = 0.f;
#pragma unroll
        for (int i = 0; i < 7; i++) {
            float trap = 0.5f * wn[i] * (hn[i] + hn[i + 1]);
            cum += wn[i];
            phicum += trap;
            bool c = (cum < x);
            wk     = c ? wn[i + 1] : wk;
            hk     = c ? hn[i + 1] : hk;
            hk1    = c ? hn[i + 2] : hk1;
            xkm1   = c ? cum      : xkm1;
            phikm1 = c ? phicum   : phikm1;
        }

        float alpha = (x - xkm1) / wk;
        float phi = phikm1 + alpha * hk * wk
                  + 0.5f * alpha * alpha * (hk1 - hk) * wk;
        phi_out[(size_t)b * SIZE_D + s] = phi;
        lsum += __logf(hk + alpha * (hk1 - hk));
    }

    red[tid] = lsum;
    __syncthreads();
    for (int o = 128; o > 0; o >>= 1) {
        if (tid < o) red[tid] += red[tid + o];
        __syncthreads();
    }
    if (tid == 0) log_out[b] = logd[b] - red[0];
}

// ---------------- launch ----------------
extern "C" void kernel_launch(void* const* d_in, const int* in_sizes, int n_in,
                              void* d_out, int out_size) {
    (void)in_sizes; (void)n_in; (void)out_size;
    const float* x_in      = (const float*)d_in[0];
    const float* x_passive = (const float*)d_in[1];
    const float* log_dens  = (const float*)d_in[2];
    const float* w1        = (const float*)d_in[3];
    const float* b1        = (const float*)d_in[4];
    const float* w2        = (const float*)d_in[5];
    const float* b2        = (const float*)d_in[6];

    float* out_phi = (float*)d_out;
    float* out_log = (float*)d_out + (size_t)NTOT;

    __half *xh, *w1t, *hbuf, *w2t, *nbuf;
    float *csum;
    cudaGetSymbolAddress((void**)&xh, g_xh);
    cudaGetSymbolAddress((void**)&w1t, g_w1t);
    cudaGetSymbolAddress((void**)&hbuf, g_h);
    cudaGetSymbolAddress((void**)&w2t, g_w2t);
    cudaGetSymbolAddress((void**)&nbuf, g_net);
    cudaGetSymbolAddress((void**)&csum, g_colsum);

    cudaFuncSetAttribute(gemm_fp16<0>, cudaFuncAttributeMaxDynamicSharedMemorySize,
                         GEMM_SMEM);
    cudaFuncSetAttribute(gemm_fp16<1>, cudaFuncAttributeMaxDynamicSharedMemorySize,
                         GEMM_SMEM);

    // 0) stats partials + x fp16 convert + colsum zero (fused)
    stat_split<<<NSTATBLK, 256>>>(x_passive, xh);
    // 1) stats finalize
    stat_pass2<<<1, 1024>>>(NSTATBLK, NTOT);
    // 2) w1 transpose + colsum accumulate
    transpose_half<1><<<dim3(HID / 64, SIZE_D / 64), 256>>>(w1, w1t, SIZE_D, HID);
    // 3) w2 transpose
    transpose_half<0><<<dim3(OUTW / 64, HID / 64), 256>>>(w2, w2t, HID, OUTW);
    // 4) GEMM1: h = tanh(xs @ w1 + b1) -> fp16
    gemm_fp16<0><<<dim3(BATCH / GBM, HID / GBN), 256, GEMM_SMEM>>>(
        xh, w1t, b1, csum, hbuf, SIZE_D, HID, SIZE_D / GBK);
    // 5) GEMM2: net = tanh(h @ w2 + b2) -> fp16
    gemm_fp16<1><<<dim3(BATCH / GBM, OUTW / GBN), 256, GEMM_SMEM>>>(
        hbuf, w2t, b2, nullptr, nbuf, HID, OUTW, HID / GBK);
    // 6) spline + per-row log-density reduction
    spline_kernel<<<BATCH, 256>>>(nbuf, x_in, log_dens, out_phi, out_log);
}